// round 2
// baseline (speedup 1.0000x reference)
#include <cuda_runtime.h>
#include <math.h>

#define NN   32768
#define EE   1048576
#define MULC 16
#define TMULC 32

// ---- scratch (static device globals; no allocation allowed) ----
__device__ int    d_count[NN + 1];
__device__ int    d_offsets[NN + 1];
__device__ int    d_cursor[NN];
__device__ int    d_sorted[EE];       // sender id per edge, grouped by receiver
__device__ float4 d_pos4[NN];
__device__ float  d_Weff[3 * 16 * 32];

// ---------------- prep: zero histogram, pack positions ----------------
__global__ void k_prep(const float* __restrict__ pos, int n) {
    int i = blockIdx.x * blockDim.x + threadIdx.x;
    if (i <= n) d_count[i] = 0;
    if (i < n) {
        d_pos4[i] = make_float4(pos[3 * i], pos[3 * i + 1], pos[3 * i + 2], 0.f);
    }
}

// ---------------- W_eff[l] = W_pre[l+1] @ W_post[l+1]  (l = 0..2) ------
__global__ void k_weff(const float* __restrict__ Wpre, const float* __restrict__ Wpost) {
    int t = blockIdx.x * blockDim.x + threadIdx.x;
    if (t >= 3 * 16 * 32) return;
    int ll = t >> 9;          // 0..2  -> irreps l = ll+1
    int u  = (t >> 5) & 15;
    int w  = t & 31;
    const float* A = Wpre  + (ll + 1) * MULC * TMULC + u * TMULC;
    const float* B = Wpost + (ll + 1) * TMULC * TMULC + w;
    float s = 0.f;
#pragma unroll
    for (int v = 0; v < TMULC; v++) s += A[v] * B[v * TMULC];
    d_Weff[t] = s;
}

// ---------------- histogram of receivers ----------------
__global__ void k_hist(const int* __restrict__ recv, int e) {
    int i = blockIdx.x * blockDim.x + threadIdx.x;
    if (i < e) atomicAdd(&d_count[recv[i]], 1);
}

// ---------------- exclusive scan over N counts (1 block, 256 thr) -------
__global__ void __launch_bounds__(256) k_scan(int n) {
    __shared__ int part[256];
    int tid = threadIdx.x;
    int per = (n + 255) / 256;          // 128 for N=32768
    int base = tid * per;
    int s = 0;
    for (int k = 0; k < per; k++) {
        int idx = base + k;
        if (idx < n) s += d_count[idx];
    }
    part[tid] = s;
    __syncthreads();
    for (int off = 1; off < 256; off <<= 1) {
        int v = part[tid];
        int a = (tid >= off) ? part[tid - off] : 0;
        __syncthreads();
        part[tid] = v + a;
        __syncthreads();
    }
    int run = (tid == 0) ? 0 : part[tid - 1];
    for (int k = 0; k < per; k++) {
        int idx = base + k;
        if (idx < n) {
            d_offsets[idx] = run;
            d_cursor[idx]  = run;
            run += d_count[idx];
        }
    }
    if (tid == 255) d_offsets[n] = run;
}

// ---------------- scatter sender ids into receiver-grouped order --------
__global__ void k_scatter(const int* __restrict__ send, const int* __restrict__ recv, int e) {
    int i = blockIdx.x * blockDim.x + threadIdx.x;
    if (i < e) {
        int r    = recv[i];
        int slot = atomicAdd(&d_cursor[r], 1);
        d_sorted[slot] = send[i];
    }
}

// ---------------- main: per-node aggregation + fused node update --------
// One warp per node. Lane owns (u = lane&15, half of the 16 SH components).
__global__ void __launch_bounds__(256)
k_main(const float* __restrict__ xin,
       const float* __restrict__ Wpre,
       const float* __restrict__ Wpost,
       const float* __restrict__ Wsc,
       float* __restrict__ out, int n) {
    __shared__ float sWeff[3 * 16 * 32];
    __shared__ float sWpre0[16 * 32];
    __shared__ float sWpost0[32 * 32];
    __shared__ float sWsc[16 * 32];
    __shared__ float sA[8][16 * 17];   // per-warp agg [u][i], stride 17 (bank-safe)
    __shared__ float sQ[8][512];       // per-warp staged output row
    __shared__ float sP0[8][32];       // per-warp gelu intermediate

    int tid = threadIdx.x;
    for (int t = tid; t < 3 * 16 * 32; t += 256) sWeff[t]  = d_Weff[t];
    for (int t = tid; t < 16 * 32;    t += 256) sWpre0[t] = Wpre[t];
    for (int t = tid; t < 32 * 32;    t += 256) sWpost0[t] = Wpost[t];
    for (int t = tid; t < 16 * 32;    t += 256) sWsc[t]   = Wsc[t];
    __syncthreads();

    int warp = tid >> 5;
    int lane = tid & 31;
    int node = blockIdx.x * 8 + warp;
    if (node >= n) return;

    float4 rp  = d_pos4[node];
    int    beg = d_offsets[node];
    int    end = d_offsets[node + 1];
    int    u   = lane & 15;
    int    hi  = lane >> 4;   // 0: SH comps 0..7, 1: comps 8..15

    float acc[8];
#pragma unroll
    for (int q = 0; q < 8; q++) acc[q] = 0.f;

    for (int t0 = beg; t0 < end; t0 += 32) {
        int myE = t0 + lane;
        int sid = (myE < end) ? d_sorted[myE] : 0;
        int cnt = end - t0;
        if (cnt > 32) cnt = 32;
        for (int k = 0; k < cnt; k++) {
            int    s  = __shfl_sync(0xffffffffu, sid, k);
            float4 sp = d_pos4[s];
            float  rx = rp.x - sp.x, ry = rp.y - sp.y, rz = rp.z - sp.z;
            float  n2 = rx * rx + ry * ry + rz * rz;
            float  iv = (n2 > 0.f) ? rsqrtf(n2) : 0.f;
            float  X = rx * iv, Y = ry * iv, Z = rz * iv;
            float  xv = xin[s * MULC + u];
            float  ys[8];
            if (hi == 0) {
                ys[0] = 1.f;
                ys[1] = 1.7320508075688772f * X;
                ys[2] = 1.7320508075688772f * Y;
                ys[3] = 1.7320508075688772f * Z;
                ys[4] = 3.872983346207417f * X * Y;
                ys[5] = 3.872983346207417f * Y * Z;
                ys[6] = 1.118033988749895f * (3.f * Z * Z - 1.f);   // 0.5*sqrt(5)
                ys[7] = 3.872983346207417f * X * Z;
            } else {
                float xx = X * X, yy = Y * Y, zz = Z * Z;
                ys[0] = 1.9364916731037085f * (xx - yy);            // 0.5*sqrt(15)
                ys[1] = 2.091650066335189f * Y * (3.f * xx - yy);   // sqrt(35/8)
                ys[2] = 10.246950765959598f * X * Y * Z;            // sqrt(105)
                ys[3] = 1.6201851746019651f * Y * (5.f * zz - 1.f); // sqrt(21/8)
                ys[4] = 1.3228756555322954f * Z * (5.f * zz - 3.f); // 0.5*sqrt(7)
                ys[5] = 1.6201851746019651f * X * (5.f * zz - 1.f);
                ys[6] = 5.123475382979799f * Z * (xx - yy);         // 0.5*sqrt(105)
                ys[7] = 2.091650066335189f * X * (xx - 3.f * yy);
            }
#pragma unroll
            for (int q = 0; q < 8; q++) acc[q] += xv * ys[q];
        }
    }

#pragma unroll
    for (int q = 0; q < 8; q++) sA[warp][u * 17 + hi * 8 + q] = acc[q];
    __syncwarp();

    // ----- node update, lane = output channel w (0..31) -----
    const float SCALE_L = 1.0f / (128.0f * 5.656854249492381f); // 1/(DENOM*sqrt(mul)*sqrt(tmul))

    // l = 1..3 via fused W_eff
#pragma unroll
    for (int lb = 0; lb < 3; lb++) {
        float wreg[16];
#pragma unroll
        for (int uu = 0; uu < 16; uu++) wreg[uu] = sWeff[(lb * 16 + uu) * 32 + lane];
        int i0  = (lb == 0) ? 1 : ((lb == 1) ? 4 : 9);
        int dim = 2 * lb + 3;
        int off = (lb == 0) ? 32 : ((lb == 1) ? 128 : 288);
#pragma unroll
        for (int j = 0; j < 7; j++) {
            if (j >= dim) break;
            int   i = i0 + j;
            float a = 0.f;
#pragma unroll
            for (int uu = 0; uu < 16; uu++) a += sA[warp][uu * 17 + i] * wreg[uu];
            sQ[warp][off + lane * dim + j] = a * SCALE_L;
        }
    }

    // l = 0 path: pre -> gelu -> post, + shortcut
    float p = 0.f;
#pragma unroll
    for (int uu = 0; uu < 16; uu++) p += sA[warp][uu * 17] * sWpre0[uu * 32 + lane];
    p *= (1.f / 128.f);                       // /DENOM * inv_in
    // exact gelu * C_GELU, C = (E[gelu(z)^2])^{-1/2} = 1.5335285
    p = 1.5335285f * 0.5f * p * (1.f + erff(p * 0.7071067811865476f));
    sP0[warp][lane] = p;
    __syncwarp();
    float q0 = 0.f;
#pragma unroll
    for (int v = 0; v < 32; v++) q0 += sP0[warp][v] * sWpost0[v * 32 + lane];
    q0 *= 0.17677669529663687f;               // 1/sqrt(32)
    float sc = 0.f;
#pragma unroll
    for (int uu = 0; uu < 16; uu++) sc += xin[node * MULC + uu] * sWsc[uu * 32 + lane];
    q0 += sc * 0.25f;                         // inv_in
    sQ[warp][lane] = q0;
    __syncwarp();

    float* op = out + (size_t)node * 512;
#pragma unroll
    for (int t = lane; t < 512; t += 32) op[t] = sQ[warp][t];
}

extern "C" void kernel_launch(void* const* d_in, const int* in_sizes, int n_in,
                              void* d_out, int out_size) {
    const float* x     = (const float*)d_in[0];
    const float* pos   = (const float*)d_in[1];
    const float* Wpre  = (const float*)d_in[2];
    const float* Wpost = (const float*)d_in[3];
    const float* Wsc   = (const float*)d_in[4];
    const int*   send  = (const int*)d_in[5];
    const int*   recv  = (const int*)d_in[6];
    float*       out   = (float*)d_out;

    int n = in_sizes[0] / MULC;   // 32768 nodes
    int e = in_sizes[5];          // 1048576 edges

    k_prep<<<(n + 256) / 256, 256>>>(pos, n);
    k_weff<<<6, 256>>>(Wpre, Wpost);
    k_hist<<<(e + 255) / 256, 256>>>(recv, e);
    k_scan<<<1, 256>>>(n);
    k_scatter<<<(e + 255) / 256, 256>>>(send, recv, e);
    k_main<<<n / 8, 256>>>(x, Wpre, Wpost, Wsc, out, n);
}

// round 3
// speedup vs baseline: 1.5292x; 1.5292x over previous
#include <cuda_runtime.h>
#include <math.h>

#define NN   32768
#define EE   1048576
#define MULC 16
#define TMULC 32

// ---- scratch (static device globals; no allocation allowed) ----
__device__ int    d_count[NN];
__device__ int    d_offsets[NN + 1];
__device__ int    d_cursor[NN];
__device__ int    d_sorted[EE];       // sender id per edge, grouped by receiver
__device__ float4 d_pos4[NN];
__device__ float  d_Weff[3 * 16 * 32];
__device__ int    d_blocksum[128];
__device__ int    d_blockpref[128];

// -------- prep: zero histogram, pack positions, build W_eff ------------
__global__ void k_prep(const float* __restrict__ pos,
                       const float* __restrict__ Wpre,
                       const float* __restrict__ Wpost, int n) {
    int i = blockIdx.x * blockDim.x + threadIdx.x;
    if (i < n) {
        d_count[i] = 0;
        d_pos4[i] = make_float4(pos[3 * i], pos[3 * i + 1], pos[3 * i + 2], 0.f);
    }
    if (i < 3 * 16 * 32) {
        int ll = i >> 9;          // 0..2  -> irreps l = ll+1
        int u  = (i >> 5) & 15;
        int w  = i & 31;
        const float* A = Wpre  + (ll + 1) * MULC * TMULC + u * TMULC;
        const float* B = Wpost + (ll + 1) * TMULC * TMULC + w;
        float s = 0.f;
#pragma unroll
        for (int v = 0; v < TMULC; v++) s += A[v] * B[v * TMULC];
        d_Weff[i] = s;
    }
}

// ---------------- histogram of receivers ----------------
__global__ void k_hist(const int* __restrict__ recv, int e) {
    int i = blockIdx.x * blockDim.x + threadIdx.x;
    if (i < e) atomicAdd(&d_count[recv[i]], 1);
}

// ------------- scan stage 1: per-block exclusive scan -------------------
__global__ void __launch_bounds__(256) k_scan1() {
    __shared__ int sh[256];
    int tid = threadIdx.x;
    int i   = blockIdx.x * 256 + tid;
    int v   = d_count[i];
    sh[tid] = v;
    __syncthreads();
#pragma unroll
    for (int off = 1; off < 256; off <<= 1) {
        int a = (tid >= off) ? sh[tid - off] : 0;
        __syncthreads();
        sh[tid] += a;
        __syncthreads();
    }
    d_offsets[i] = sh[tid] - v;           // partial (block-local) exclusive
    if (tid == 255) d_blocksum[blockIdx.x] = sh[255];
}

// ------------- scan stage 2: scan the 128 block sums --------------------
__global__ void __launch_bounds__(128) k_scan2() {
    __shared__ int sh[128];
    int tid = threadIdx.x;
    int v   = d_blocksum[tid];
    sh[tid] = v;
    __syncthreads();
#pragma unroll
    for (int off = 1; off < 128; off <<= 1) {
        int a = (tid >= off) ? sh[tid - off] : 0;
        __syncthreads();
        sh[tid] += a;
        __syncthreads();
    }
    d_blockpref[tid] = sh[tid] - v;
}

// ------------- scan stage 3: fixup + init cursor ------------------------
__global__ void __launch_bounds__(256) k_scan3(int n, int e) {
    int tid = threadIdx.x;
    int i   = blockIdx.x * 256 + tid;
    int o   = d_offsets[i] + d_blockpref[blockIdx.x];
    d_offsets[i] = o;
    d_cursor[i]  = o;
    if (i == 0) d_offsets[n] = e;
}

// ---------------- scatter sender ids into receiver-grouped order --------
__global__ void k_scatter(const int* __restrict__ send, const int* __restrict__ recv, int e) {
    int i = blockIdx.x * blockDim.x + threadIdx.x;
    if (i < e) {
        int r    = recv[i];
        int slot = atomicAdd(&d_cursor[r], 1);
        d_sorted[slot] = send[i];
    }
}

// ------------- per-edge accumulation (one SH half per lane) -------------
__device__ __forceinline__ void edge_acc(float4 rp, float4 sp, float xv,
                                         int hi, float* acc) {
    float rx = rp.x - sp.x, ry = rp.y - sp.y, rz = rp.z - sp.z;
    float n2 = rx * rx + ry * ry + rz * rz;
    float iv = (n2 > 0.f) ? rsqrtf(n2) : 0.f;
    float X = rx * iv, Y = ry * iv, Z = rz * iv;
    float ys[8];
    if (hi == 0) {
        ys[0] = 1.f;
        ys[1] = 1.7320508075688772f * X;
        ys[2] = 1.7320508075688772f * Y;
        ys[3] = 1.7320508075688772f * Z;
        ys[4] = 3.872983346207417f * X * Y;
        ys[5] = 3.872983346207417f * Y * Z;
        ys[6] = 1.118033988749895f * (3.f * Z * Z - 1.f);   // 0.5*sqrt(5)
        ys[7] = 3.872983346207417f * X * Z;
    } else {
        float xx = X * X, yy = Y * Y, zz = Z * Z;
        ys[0] = 1.9364916731037085f * (xx - yy);            // 0.5*sqrt(15)
        ys[1] = 2.091650066335189f * Y * (3.f * xx - yy);   // sqrt(35/8)
        ys[2] = 10.246950765959598f * X * Y * Z;            // sqrt(105)
        ys[3] = 1.6201851746019651f * Y * (5.f * zz - 1.f); // sqrt(21/8)
        ys[4] = 1.3228756555322954f * Z * (5.f * zz - 3.f); // 0.5*sqrt(7)
        ys[5] = 1.6201851746019651f * X * (5.f * zz - 1.f);
        ys[6] = 5.123475382979799f * Z * (xx - yy);         // 0.5*sqrt(105)
        ys[7] = 2.091650066335189f * X * (xx - 3.f * yy);
    }
#pragma unroll
    for (int q = 0; q < 8; q++) acc[q] += xv * ys[q];
}

// ---------------- main: per-node aggregation + fused node update --------
// One warp per node. Lane owns (u = lane&15, half of the 16 SH components).
__global__ void __launch_bounds__(256)
k_main(const float* __restrict__ xin,
       const float* __restrict__ Wpre,
       const float* __restrict__ Wpost,
       const float* __restrict__ Wsc,
       float* __restrict__ out, int n) {
    __shared__ float sWeff[3 * 16 * 32];
    __shared__ float sWpre0[16 * 32];
    __shared__ float sWpost0[32 * 32];
    __shared__ float sWsc[16 * 32];
    __shared__ float sA[8][16 * 17];   // per-warp agg [u][i], stride 17 (bank-safe)
    __shared__ float sQ[8][512];       // per-warp staged output row
    __shared__ float sP0[8][32];       // per-warp gelu intermediate

    int tid = threadIdx.x;
    for (int t = tid; t < 3 * 16 * 32; t += 256) sWeff[t]  = d_Weff[t];
    for (int t = tid; t < 16 * 32;    t += 256) sWpre0[t] = Wpre[t];
    for (int t = tid; t < 32 * 32;    t += 256) sWpost0[t] = Wpost[t];
    for (int t = tid; t < 16 * 32;    t += 256) sWsc[t]   = Wsc[t];
    __syncthreads();

    int warp = tid >> 5;
    int lane = tid & 31;
    int node = blockIdx.x * 8 + warp;
    if (node >= n) return;

    float4 rp  = d_pos4[node];
    int    beg = d_offsets[node];
    int    end = d_offsets[node + 1];
    int    u   = lane & 15;
    int    hi  = lane >> 4;   // 0: SH comps 0..7, 1: comps 8..15

    float acc[8];
#pragma unroll
    for (int q = 0; q < 8; q++) acc[q] = 0.f;

    for (int t0 = beg; t0 < end; t0 += 32) {
        int myE = t0 + lane;
        int sid = (myE < end) ? d_sorted[myE] : 0;
        int cnt = end - t0;
        if (cnt > 32) cnt = 32;
        int k = 0;
        // 4-deep software pipeline: 8 independent loads, then 4 edge computes
        for (; k + 4 <= cnt; k += 4) {
            int s0 = __shfl_sync(0xffffffffu, sid, k);
            int s1 = __shfl_sync(0xffffffffu, sid, k + 1);
            int s2 = __shfl_sync(0xffffffffu, sid, k + 2);
            int s3 = __shfl_sync(0xffffffffu, sid, k + 3);
            float4 p0 = d_pos4[s0];
            float4 p1 = d_pos4[s1];
            float4 p2 = d_pos4[s2];
            float4 p3 = d_pos4[s3];
            float  x0 = xin[s0 * MULC + u];
            float  x1 = xin[s1 * MULC + u];
            float  x2 = xin[s2 * MULC + u];
            float  x3 = xin[s3 * MULC + u];
            edge_acc(rp, p0, x0, hi, acc);
            edge_acc(rp, p1, x1, hi, acc);
            edge_acc(rp, p2, x2, hi, acc);
            edge_acc(rp, p3, x3, hi, acc);
        }
        for (; k < cnt; k++) {
            int    s  = __shfl_sync(0xffffffffu, sid, k);
            float4 sp = d_pos4[s];
            float  xv = xin[s * MULC + u];
            edge_acc(rp, sp, xv, hi, acc);
        }
    }

#pragma unroll
    for (int q = 0; q < 8; q++) sA[warp][u * 17 + hi * 8 + q] = acc[q];
    __syncwarp();

    // ----- node update, lane = output channel w (0..31) -----
    const float SCALE_L = 1.0f / (128.0f * 5.656854249492381f); // 1/(DENOM*sqrt(mul)*sqrt(tmul))

    // l = 1..3 via fused W_eff
#pragma unroll
    for (int lb = 0; lb < 3; lb++) {
        float wreg[16];
#pragma unroll
        for (int uu = 0; uu < 16; uu++) wreg[uu] = sWeff[(lb * 16 + uu) * 32 + lane];
        int i0  = (lb == 0) ? 1 : ((lb == 1) ? 4 : 9);
        int dim = 2 * lb + 3;
        int off = (lb == 0) ? 32 : ((lb == 1) ? 128 : 288);
#pragma unroll
        for (int j = 0; j < 7; j++) {
            if (j >= dim) break;
            int   i = i0 + j;
            float a = 0.f;
#pragma unroll
            for (int uu = 0; uu < 16; uu++) a += sA[warp][uu * 17 + i] * wreg[uu];
            sQ[warp][off + lane * dim + j] = a * SCALE_L;
        }
    }

    // l = 0 path: pre -> gelu -> post, + shortcut
    float p = 0.f;
#pragma unroll
    for (int uu = 0; uu < 16; uu++) p += sA[warp][uu * 17] * sWpre0[uu * 32 + lane];
    p *= (1.f / 128.f);                       // /DENOM * inv_in
    // exact gelu * C_GELU, C = (E[gelu(z)^2])^{-1/2} = 1.5335285
    p = 1.5335285f * 0.5f * p * (1.f + erff(p * 0.7071067811865476f));
    sP0[warp][lane] = p;
    __syncwarp();
    float q0 = 0.f;
#pragma unroll
    for (int v = 0; v < 32; v++) q0 += sP0[warp][v] * sWpost0[v * 32 + lane];
    q0 *= 0.17677669529663687f;               // 1/sqrt(32)
    float sc = 0.f;
#pragma unroll
    for (int uu = 0; uu < 16; uu++) sc += xin[node * MULC + uu] * sWsc[uu * 32 + lane];
    q0 += sc * 0.25f;                         // inv_in
    sQ[warp][lane] = q0;
    __syncwarp();

    float* op = out + (size_t)node * 512;
#pragma unroll
    for (int t = lane; t < 512; t += 32) op[t] = sQ[warp][t];
}

extern "C" void kernel_launch(void* const* d_in, const int* in_sizes, int n_in,
                              void* d_out, int out_size) {
    const float* x     = (const float*)d_in[0];
    const float* pos   = (const float*)d_in[1];
    const float* Wpre  = (const float*)d_in[2];
    const float* Wpost = (const float*)d_in[3];
    const float* Wsc   = (const float*)d_in[4];
    const int*   send  = (const int*)d_in[5];
    const int*   recv  = (const int*)d_in[6];
    float*       out   = (float*)d_out;

    int n = in_sizes[0] / MULC;   // 32768 nodes
    int e = in_sizes[5];          // 1048576 edges

    k_prep<<<(n + 255) / 256, 256>>>(pos, Wpre, Wpost, n);
    k_hist<<<(e + 255) / 256, 256>>>(recv, e);
    k_scan1<<<128, 256>>>();
    k_scan2<<<1, 128>>>();
    k_scan3<<<128, 256>>>(n, e);
    k_scatter<<<(e + 255) / 256, 256>>>(send, recv, e);
    k_main<<<n / 8, 256>>>(x, Wpre, Wpost, Wsc, out, n);
}

// round 4
// speedup vs baseline: 1.6308x; 1.0664x over previous
#include <cuda_runtime.h>
#include <math.h>

#define NN   32768
#define EE   1048576
#define MULC 16
#define TMULC 32

// ---- scratch (static device globals; no allocation allowed) ----
__device__ int    d_count[NN];
__device__ int    d_offsets[NN + 1];
__device__ int    d_cursor[NN];
__device__ int    d_sorted[EE];       // sender id per edge, grouped by receiver
__device__ float4 d_pos4[NN];
__device__ float  d_Weff[3 * 16 * 32];
__device__ int    d_blocksum[128];
__device__ int    d_blockpref[128];

// -------- prep: zero histogram, pack positions, build W_eff ------------
__global__ void k_prep(const float* __restrict__ pos,
                       const float* __restrict__ Wpre,
                       const float* __restrict__ Wpost, int n) {
    int i = blockIdx.x * blockDim.x + threadIdx.x;
    if (i < n) {
        d_count[i] = 0;
        d_pos4[i] = make_float4(pos[3 * i], pos[3 * i + 1], pos[3 * i + 2], 0.f);
    }
    if (i < 3 * 16 * 32) {
        int ll = i >> 9;          // 0..2  -> irreps l = ll+1
        int u  = (i >> 5) & 15;
        int w  = i & 31;
        const float* A = Wpre  + (ll + 1) * MULC * TMULC + u * TMULC;
        const float* B = Wpost + (ll + 1) * TMULC * TMULC + w;
        float s = 0.f;
#pragma unroll
        for (int v = 0; v < TMULC; v++) s += A[v] * B[v * TMULC];
        d_Weff[i] = s;
    }
}

// ---------------- histogram of receivers (4 edges/thread) ---------------
__global__ void k_hist(const int4* __restrict__ recv4, int e4) {
    int i = blockIdx.x * blockDim.x + threadIdx.x;
    if (i < e4) {
        int4 r = recv4[i];
        atomicAdd(&d_count[r.x], 1);
        atomicAdd(&d_count[r.y], 1);
        atomicAdd(&d_count[r.z], 1);
        atomicAdd(&d_count[r.w], 1);
    }
}

// ------------- scan stage 1: per-block exclusive scan -------------------
__global__ void __launch_bounds__(256) k_scan1() {
    __shared__ int sh[256];
    int tid = threadIdx.x;
    int i   = blockIdx.x * 256 + tid;
    int v   = d_count[i];
    sh[tid] = v;
    __syncthreads();
#pragma unroll
    for (int off = 1; off < 256; off <<= 1) {
        int a = (tid >= off) ? sh[tid - off] : 0;
        __syncthreads();
        sh[tid] += a;
        __syncthreads();
    }
    d_offsets[i] = sh[tid] - v;           // partial (block-local) exclusive
    if (tid == 255) d_blocksum[blockIdx.x] = sh[255];
}

// ------------- scan stage 2: scan the 128 block sums --------------------
__global__ void __launch_bounds__(128) k_scan2() {
    __shared__ int sh[128];
    int tid = threadIdx.x;
    int v   = d_blocksum[tid];
    sh[tid] = v;
    __syncthreads();
#pragma unroll
    for (int off = 1; off < 128; off <<= 1) {
        int a = (tid >= off) ? sh[tid - off] : 0;
        __syncthreads();
        sh[tid] += a;
        __syncthreads();
    }
    d_blockpref[tid] = sh[tid] - v;
}

// ------------- scan stage 3: fixup + init cursor ------------------------
__global__ void __launch_bounds__(256) k_scan3(int n, int e) {
    int tid = threadIdx.x;
    int i   = blockIdx.x * 256 + tid;
    int o   = d_offsets[i] + d_blockpref[blockIdx.x];
    d_offsets[i] = o;
    d_cursor[i]  = o;
    if (i == 0) d_offsets[n] = e;
}

// -------- scatter sender ids into receiver-grouped order (4/thread) -----
__global__ void k_scatter(const int4* __restrict__ send4, const int4* __restrict__ recv4, int e4) {
    int i = blockIdx.x * blockDim.x + threadIdx.x;
    if (i < e4) {
        int4 s = send4[i];
        int4 r = recv4[i];
        d_sorted[atomicAdd(&d_cursor[r.x], 1)] = s.x;
        d_sorted[atomicAdd(&d_cursor[r.y], 1)] = s.y;
        d_sorted[atomicAdd(&d_cursor[r.z], 1)] = s.z;
        d_sorted[atomicAdd(&d_cursor[r.w], 1)] = s.w;
    }
}

// ------------- per-edge raw-monomial accumulation ------------------------
// hi=0 accumulates { 1, X, Y, Z, XY, YZ, ZZ, XZ } * xv
// hi=1 accumulates { P, YP, XP, Y*zz, X*zz, Z*zz, ZP, XYZ } * xv, P = X^2-Y^2
// SH normalization constants + curvature fixups applied ONCE per node.
__device__ __forceinline__ void edge_acc(float4 rp, float4 sp, float xv,
                                         int hi, float* acc) {
    float rx = rp.x - sp.x, ry = rp.y - sp.y, rz = rp.z - sp.z;
    float n2 = rx * rx + ry * ry + rz * rz;
    float iv = (n2 > 0.f) ? rsqrtf(n2) : 0.f;
    float X = rx * iv, Y = ry * iv, Z = rz * iv;
    if (hi == 0) {
        acc[0] += xv;
        acc[1] += xv * X;
        acc[2] += xv * Y;
        acc[3] += xv * Z;
        float XY = X * Y, YZ = Y * Z, ZZ = Z * Z, XZ = X * Z;
        acc[4] += xv * XY;
        acc[5] += xv * YZ;
        acc[6] += xv * ZZ;
        acc[7] += xv * XZ;
    } else {
        float YY = Y * Y, ZZ = Z * Z;
        float P  = fmaf(X, X, -YY);
        float XY = X * Y;
        acc[0] += xv * P;
        acc[1] += xv * (Y * P);
        acc[2] += xv * (X * P);
        acc[3] += xv * (Y * ZZ);
        acc[4] += xv * (X * ZZ);
        acc[5] += xv * (Z * ZZ);
        acc[6] += xv * (Z * P);
        acc[7] += xv * (XY * Z);
    }
}

// ---------------- main: per-node aggregation + fused node update --------
// One warp per node. Lane owns (u = lane&15, half of the 16 SH components).
__global__ void __launch_bounds__(256)
k_main(const float* __restrict__ xin,
       const float* __restrict__ Wpre,
       const float* __restrict__ Wpost,
       const float* __restrict__ Wsc,
       float* __restrict__ out, int n) {
    __shared__ float sWeff[3 * 16 * 32];
    __shared__ float sWpre0[16 * 32];
    __shared__ float sWpost0[32 * 32];
    __shared__ float sWsc[16 * 32];
    __shared__ float sA[8][16 * 17];   // per-warp agg [u][i], stride 17 (bank-safe)
    __shared__ float sQ[8][512];       // per-warp staged output row
    __shared__ float sP0[8][32];       // per-warp gelu intermediate

    int tid = threadIdx.x;
    for (int t = tid; t < 3 * 16 * 32; t += 256) sWeff[t]  = d_Weff[t];
    for (int t = tid; t < 16 * 32;    t += 256) sWpre0[t] = Wpre[t];
    for (int t = tid; t < 32 * 32;    t += 256) sWpost0[t] = Wpost[t];
    for (int t = tid; t < 16 * 32;    t += 256) sWsc[t]   = Wsc[t];
    __syncthreads();

    int warp = tid >> 5;
    int lane = tid & 31;
    int node = blockIdx.x * 8 + warp;
    if (node >= n) return;

    float4 rp  = d_pos4[node];
    int    beg = d_offsets[node];
    int    end = d_offsets[node + 1];
    int    u   = lane & 15;
    int    hi  = lane >> 4;   // 0: SH comps 0..7, 1: comps 8..15

    float acc[8];
#pragma unroll
    for (int q = 0; q < 8; q++) acc[q] = 0.f;

    for (int t0 = beg; t0 < end; t0 += 32) {
        int myE = t0 + lane;
        int sid = (myE < end) ? d_sorted[myE] : 0;
        int cnt = end - t0;
        if (cnt > 32) cnt = 32;
        int k = 0;
        // 4-deep software pipeline: 8 independent loads, then 4 edge computes
        for (; k + 4 <= cnt; k += 4) {
            int s0 = __shfl_sync(0xffffffffu, sid, k);
            int s1 = __shfl_sync(0xffffffffu, sid, k + 1);
            int s2 = __shfl_sync(0xffffffffu, sid, k + 2);
            int s3 = __shfl_sync(0xffffffffu, sid, k + 3);
            float4 p0 = d_pos4[s0];
            float4 p1 = d_pos4[s1];
            float4 p2 = d_pos4[s2];
            float4 p3 = d_pos4[s3];
            float  x0 = xin[s0 * MULC + u];
            float  x1 = xin[s1 * MULC + u];
            float  x2 = xin[s2 * MULC + u];
            float  x3 = xin[s3 * MULC + u];
            edge_acc(rp, p0, x0, hi, acc);
            edge_acc(rp, p1, x1, hi, acc);
            edge_acc(rp, p2, x2, hi, acc);
            edge_acc(rp, p3, x3, hi, acc);
        }
        for (; k < cnt; k++) {
            int    s  = __shfl_sync(0xffffffffu, sid, k);
            float4 sp = d_pos4[s];
            float  xv = xin[s * MULC + u];
            edge_acc(rp, sp, xv, hi, acc);
        }
    }

    // ---- reconstruct normalized SH aggregates (once per node) ----
    // hi=1 lane needs raw first moments from its hi=0 partner (same u).
    float AX = __shfl_sync(0xffffffffu, acc[1], u);
    float AY = __shfl_sync(0xffffffffu, acc[2], u);
    float AZ = __shfl_sync(0xffffffffu, acc[3], u);
    float ys[8];
    if (hi == 0) {
        ys[0] = acc[0];
        ys[1] = 1.7320508075688772f * acc[1];
        ys[2] = 1.7320508075688772f * acc[2];
        ys[3] = 1.7320508075688772f * acc[3];
        ys[4] = 3.872983346207417f * acc[4];
        ys[5] = 3.872983346207417f * acc[5];
        ys[6] = 1.118033988749895f * (3.f * acc[6] - acc[0]);        // 0.5*sqrt(5)
        ys[7] = 3.872983346207417f * acc[7];
    } else {
        ys[0] = 1.9364916731037085f * acc[0];                        // 0.5*sqrt(15)
        ys[1] = 2.091650066335189f * (AY - acc[3] + 2.f * acc[1]);   // sqrt(35/8): y(3xx-yy)
        ys[2] = 10.246950765959598f * acc[7];                        // sqrt(105)
        ys[3] = 1.6201851746019651f * (5.f * acc[3] - AY);           // sqrt(21/8)
        ys[4] = 1.3228756555322954f * (5.f * acc[5] - 3.f * AZ);     // 0.5*sqrt(7)
        ys[5] = 1.6201851746019651f * (5.f * acc[4] - AX);
        ys[6] = 5.123475382979799f * acc[6];                         // 0.5*sqrt(105)
        ys[7] = 2.091650066335189f * (acc[4] + 2.f * acc[2] - AX);   // x(xx-3yy)
    }
#pragma unroll
    for (int q = 0; q < 8; q++) sA[warp][u * 17 + hi * 8 + q] = ys[q];
    __syncwarp();

    // ----- node update, lane = output channel w (0..31) -----
    const float SCALE_L = 1.0f / (128.0f * 5.656854249492381f); // 1/(DENOM*sqrt(mul)*sqrt(tmul))

    // l = 1..3 via fused W_eff
#pragma unroll
    for (int lb = 0; lb < 3; lb++) {
        float wreg[16];
#pragma unroll
        for (int uu = 0; uu < 16; uu++) wreg[uu] = sWeff[(lb * 16 + uu) * 32 + lane];
        int i0  = (lb == 0) ? 1 : ((lb == 1) ? 4 : 9);
        int dim = 2 * lb + 3;
        int off = (lb == 0) ? 32 : ((lb == 1) ? 128 : 288);
#pragma unroll
        for (int j = 0; j < 7; j++) {
            if (j >= dim) break;
            int   i = i0 + j;
            float a = 0.f;
#pragma unroll
            for (int uu = 0; uu < 16; uu++) a += sA[warp][uu * 17 + i] * wreg[uu];
            sQ[warp][off + lane * dim + j] = a * SCALE_L;
        }
    }

    // l = 0 path: pre -> gelu -> post, + shortcut
    float p = 0.f;
#pragma unroll
    for (int uu = 0; uu < 16; uu++) p += sA[warp][uu * 17] * sWpre0[uu * 32 + lane];
    p *= (1.f / 128.f);                       // /DENOM * inv_in
    // exact gelu * C_GELU, C = (E[gelu(z)^2])^{-1/2} = 1.5335285
    p = 1.5335285f * 0.5f * p * (1.f + erff(p * 0.7071067811865476f));
    sP0[warp][lane] = p;
    __syncwarp();
    float q0 = 0.f;
#pragma unroll
    for (int v = 0; v < 32; v++) q0 += sP0[warp][v] * sWpost0[v * 32 + lane];
    q0 *= 0.17677669529663687f;               // 1/sqrt(32)
    float sc = 0.f;
#pragma unroll
    for (int uu = 0; uu < 16; uu++) sc += xin[node * MULC + uu] * sWsc[uu * 32 + lane];
    q0 += sc * 0.25f;                         // inv_in
    sQ[warp][lane] = q0;
    __syncwarp();

    float* op = out + (size_t)node * 512;
#pragma unroll
    for (int t = lane; t < 512; t += 32) op[t] = sQ[warp][t];
}

extern "C" void kernel_launch(void* const* d_in, const int* in_sizes, int n_in,
                              void* d_out, int out_size) {
    const float* x     = (const float*)d_in[0];
    const float* pos   = (const float*)d_in[1];
    const float* Wpre  = (const float*)d_in[2];
    const float* Wpost = (const float*)d_in[3];
    const float* Wsc   = (const float*)d_in[4];
    const int*   send  = (const int*)d_in[5];
    const int*   recv  = (const int*)d_in[6];
    float*       out   = (float*)d_out;

    int n  = in_sizes[0] / MULC;  // 32768 nodes
    int e  = in_sizes[5];         // 1048576 edges
    int e4 = e / 4;

    k_prep<<<(n + 255) / 256, 256>>>(pos, Wpre, Wpost, n);
    k_hist<<<(e4 + 255) / 256, 256>>>((const int4*)recv, e4);
    k_scan1<<<128, 256>>>();
    k_scan2<<<1, 128>>>();
    k_scan3<<<128, 256>>>(n, e);
    k_scatter<<<(e4 + 255) / 256, 256>>>((const int4*)send, (const int4*)recv, e4);
    k_main<<<n / 8, 256>>>(x, Wpre, Wpost, Wsc, out, n);
}

// round 5
// speedup vs baseline: 1.8526x; 1.1360x over previous
#include <cuda_runtime.h>
#include <math.h>

#define NN   32768
#define EE   1048576
#define MULC 16
#define TMULC 32

// ---- scratch (static device globals; no allocation allowed) ----
__device__ int    d_count[NN];
__device__ int    d_offsets[NN + 1];
__device__ int    d_cursor[NN];
__device__ int    d_sorted[EE];       // sender id per edge, grouped by receiver
__device__ float4 d_pos4[NN];
__device__ float  d_Weff[3 * 16 * 32];
__device__ int    d_blocksum[128];
__device__ int    d_blockpref[128];

// -------- prep: zero histogram, pack positions, build W_eff ------------
__global__ void k_prep(const float* __restrict__ pos,
                       const float* __restrict__ Wpre,
                       const float* __restrict__ Wpost, int n) {
    int i = blockIdx.x * blockDim.x + threadIdx.x;
    if (i < n) {
        d_count[i] = 0;
        d_pos4[i] = make_float4(pos[3 * i], pos[3 * i + 1], pos[3 * i + 2], 0.f);
    }
    if (i < 3 * 16 * 32) {
        int ll = i >> 9;          // 0..2  -> irreps l = ll+1
        int u  = (i >> 5) & 15;
        int w  = i & 31;
        const float* A = Wpre  + (ll + 1) * MULC * TMULC + u * TMULC;
        const float* B = Wpost + (ll + 1) * TMULC * TMULC + w;
        float s = 0.f;
#pragma unroll
        for (int v = 0; v < TMULC; v++) s += A[v] * B[v * TMULC];
        d_Weff[i] = s;
    }
}

// ---------------- histogram of receivers (4 edges/thread) ---------------
__global__ void k_hist(const int4* __restrict__ recv4, int e4) {
    int i = blockIdx.x * blockDim.x + threadIdx.x;
    if (i < e4) {
        int4 r = recv4[i];
        atomicAdd(&d_count[r.x], 1);
        atomicAdd(&d_count[r.y], 1);
        atomicAdd(&d_count[r.z], 1);
        atomicAdd(&d_count[r.w], 1);
    }
}

// ------------- scan stage 1: per-block exclusive scan -------------------
__global__ void __launch_bounds__(256) k_scan1() {
    __shared__ int sh[256];
    int tid = threadIdx.x;
    int i   = blockIdx.x * 256 + tid;
    int v   = d_count[i];
    sh[tid] = v;
    __syncthreads();
#pragma unroll
    for (int off = 1; off < 256; off <<= 1) {
        int a = (tid >= off) ? sh[tid - off] : 0;
        __syncthreads();
        sh[tid] += a;
        __syncthreads();
    }
    d_offsets[i] = sh[tid] - v;           // partial (block-local) exclusive
    if (tid == 255) d_blocksum[blockIdx.x] = sh[255];
}

// ------------- scan stage 2: scan the 128 block sums --------------------
__global__ void __launch_bounds__(128) k_scan2() {
    __shared__ int sh[128];
    int tid = threadIdx.x;
    int v   = d_blocksum[tid];
    sh[tid] = v;
    __syncthreads();
#pragma unroll
    for (int off = 1; off < 128; off <<= 1) {
        int a = (tid >= off) ? sh[tid - off] : 0;
        __syncthreads();
        sh[tid] += a;
        __syncthreads();
    }
    d_blockpref[tid] = sh[tid] - v;
}

// ------------- scan stage 3: fixup + init cursor ------------------------
__global__ void __launch_bounds__(256) k_scan3(int n, int e) {
    int tid = threadIdx.x;
    int i   = blockIdx.x * 256 + tid;
    int o   = d_offsets[i] + d_blockpref[blockIdx.x];
    d_offsets[i] = o;
    d_cursor[i]  = o;
    if (i == 0) d_offsets[n] = e;
}

// -------- scatter sender ids into receiver-grouped order (4/thread) -----
__global__ void k_scatter(const int4* __restrict__ send4, const int4* __restrict__ recv4, int e4) {
    int i = blockIdx.x * blockDim.x + threadIdx.x;
    if (i < e4) {
        int4 s = send4[i];
        int4 r = recv4[i];
        d_sorted[atomicAdd(&d_cursor[r.x], 1)] = s.x;
        d_sorted[atomicAdd(&d_cursor[r.y], 1)] = s.y;
        d_sorted[atomicAdd(&d_cursor[r.z], 1)] = s.z;
        d_sorted[atomicAdd(&d_cursor[r.w], 1)] = s.w;
    }
}

// ---------------- main: per-node aggregation + fused node update --------
// One warp per node. Lane = (h = lane>>4, u = lane&15). Each round, half h
// processes edge 2k+h: all 32 lanes run the SAME instruction stream (no
// divergence); each lane accumulates all 16 raw monomials for its u.
__global__ void __launch_bounds__(256)
k_main(const float* __restrict__ xin,
       const float* __restrict__ Wpre,
       const float* __restrict__ Wpost,
       const float* __restrict__ Wsc,
       float* __restrict__ out, int n) {
    __shared__ float sWeff[3 * 16 * 32];
    __shared__ float sWpre0[16 * 32];
    __shared__ float sWpost0[32 * 32];
    __shared__ float sWsc[16 * 32];
    __shared__ float sA[8][16 * 17];   // per-warp agg [u][comp], stride 17
    __shared__ float sQ[8][512];       // per-warp staged output row
    __shared__ float sP0[8][32];       // per-warp gelu intermediate

    int tid = threadIdx.x;
    for (int t = tid; t < 3 * 16 * 32; t += 256) sWeff[t]  = d_Weff[t];
    for (int t = tid; t < 16 * 32;    t += 256) sWpre0[t] = Wpre[t];
    for (int t = tid; t < 32 * 32;    t += 256) sWpost0[t] = Wpost[t];
    for (int t = tid; t < 16 * 32;    t += 256) sWsc[t]   = Wsc[t];
    __syncthreads();

    int warp = tid >> 5;
    int lane = tid & 31;
    int node = blockIdx.x * 8 + warp;
    if (node >= n) return;

    float4 rp  = d_pos4[node];
    int    beg = d_offsets[node];
    int    end = d_offsets[node + 1];
    int    u   = lane & 15;
    int    h   = lane >> 4;

    // acc[c]: raw monomial aggregates for this lane's u, half-h edges only.
    // c: 0=1 1=X 2=Y 3=Z 4=XY 5=YZ 6=ZZ 7=XZ
    //    8=P 9=YP 10=XP 11=Y*ZZ 12=X*ZZ 13=Z*ZZ 14=ZP 15=XYZ   (P=X^2-Y^2)
    float acc[16];
#pragma unroll
    for (int c = 0; c < 16; c++) acc[c] = 0.f;

    for (int t0 = beg; t0 < end; t0 += 32) {
        int myE = t0 + lane;
        int sid = (myE < end) ? d_sorted[myE] : 0;
        int cnt = end - t0;
        if (cnt > 32) cnt = 32;
        int rounds = (cnt + 1) >> 1;
#pragma unroll 4
        for (int k = 0; k < rounds; k++) {
            int    ei = 2 * k + h;
            int    s  = __shfl_sync(0xffffffffu, sid, ei);
            float4 sp = d_pos4[s];
            float  xv = (ei < cnt) ? xin[s * MULC + u] : 0.f;
            float rx = rp.x - sp.x, ry = rp.y - sp.y, rz = rp.z - sp.z;
            float n2 = rx * rx + ry * ry + rz * rz;
            float iv = (n2 > 0.f) ? rsqrtf(n2) : 0.f;
            float X = rx * iv, Y = ry * iv, Z = rz * iv;
            float XY = X * Y, YZ = Y * Z, ZZ = Z * Z, XZ = X * Z;
            float P  = fmaf(X, X, -(Y * Y));
            acc[0] += xv;
            acc[1] = fmaf(xv, X, acc[1]);
            acc[2] = fmaf(xv, Y, acc[2]);
            acc[3] = fmaf(xv, Z, acc[3]);
            acc[4] = fmaf(xv, XY, acc[4]);
            acc[5] = fmaf(xv, YZ, acc[5]);
            acc[6] = fmaf(xv, ZZ, acc[6]);
            acc[7] = fmaf(xv, XZ, acc[7]);
            acc[8]  = fmaf(xv, P, acc[8]);
            acc[9]  = fmaf(xv, Y * P, acc[9]);
            acc[10] = fmaf(xv, X * P, acc[10]);
            acc[11] = fmaf(xv, Y * ZZ, acc[11]);
            acc[12] = fmaf(xv, X * ZZ, acc[12]);
            acc[13] = fmaf(xv, Z * ZZ, acc[13]);
            acc[14] = fmaf(xv, Z * P, acc[14]);
            acc[15] = fmaf(xv, XY * Z, acc[15]);
        }
    }

    // merge the two half-edge partial sums (lanes u and u+16 both end full)
#pragma unroll
    for (int c = 0; c < 16; c++) acc[c] += __shfl_xor_sync(0xffffffffu, acc[c], 16);

    // ---- reconstruct normalized SH aggregates; lane (u,h) emits comps h*8.. ----
    float ys[8];
    if (h == 0) {
        ys[0] = acc[0];
        ys[1] = 1.7320508075688772f * acc[1];
        ys[2] = 1.7320508075688772f * acc[2];
        ys[3] = 1.7320508075688772f * acc[3];
        ys[4] = 3.872983346207417f * acc[4];
        ys[5] = 3.872983346207417f * acc[5];
        ys[6] = 1.118033988749895f * (3.f * acc[6] - acc[0]);          // 0.5*sqrt(5)
        ys[7] = 3.872983346207417f * acc[7];
    } else {
        ys[0] = 1.9364916731037085f * acc[8];                          // 0.5*sqrt(15)
        ys[1] = 2.091650066335189f * (acc[2] - acc[11] + 2.f * acc[9]); // y(3xx-yy)
        ys[2] = 10.246950765959598f * acc[15];                         // sqrt(105)
        ys[3] = 1.6201851746019651f * (5.f * acc[11] - acc[2]);        // sqrt(21/8)
        ys[4] = 1.3228756555322954f * (5.f * acc[13] - 3.f * acc[3]);  // 0.5*sqrt(7)
        ys[5] = 1.6201851746019651f * (5.f * acc[12] - acc[1]);
        ys[6] = 5.123475382979799f * acc[14];                          // 0.5*sqrt(105)
        ys[7] = 2.091650066335189f * (2.f * acc[10] + acc[12] - acc[1]); // x(xx-3yy)
    }
#pragma unroll
    for (int q = 0; q < 8; q++) sA[warp][u * 17 + h * 8 + q] = ys[q];
    __syncwarp();

    // ----- node update, lane = output channel w (0..31) -----
    const float SCALE_L = 1.0f / (128.0f * 5.656854249492381f); // 1/(DENOM*sqrt(mul)*sqrt(tmul))

    // l = 1..3 via fused W_eff
#pragma unroll
    for (int lb = 0; lb < 3; lb++) {
        float wreg[16];
#pragma unroll
        for (int uu = 0; uu < 16; uu++) wreg[uu] = sWeff[(lb * 16 + uu) * 32 + lane];
        int i0  = (lb == 0) ? 1 : ((lb == 1) ? 4 : 9);
        int dim = 2 * lb + 3;
        int off = (lb == 0) ? 32 : ((lb == 1) ? 128 : 288);
#pragma unroll
        for (int j = 0; j < 7; j++) {
            if (j >= dim) break;
            int   i = i0 + j;
            float a = 0.f;
#pragma unroll
            for (int uu = 0; uu < 16; uu++) a += sA[warp][uu * 17 + i] * wreg[uu];
            sQ[warp][off + lane * dim + j] = a * SCALE_L;
        }
    }

    // l = 0 path: pre -> gelu -> post, + shortcut
    float p = 0.f;
#pragma unroll
    for (int uu = 0; uu < 16; uu++) p += sA[warp][uu * 17] * sWpre0[uu * 32 + lane];
    p *= (1.f / 128.f);                       // /DENOM * inv_in
    // exact gelu * C_GELU, C = (E[gelu(z)^2])^{-1/2} = 1.5335285
    p = 1.5335285f * 0.5f * p * (1.f + erff(p * 0.7071067811865476f));
    sP0[warp][lane] = p;
    __syncwarp();
    float q0 = 0.f;
#pragma unroll
    for (int v = 0; v < 32; v++) q0 += sP0[warp][v] * sWpost0[v * 32 + lane];
    q0 *= 0.17677669529663687f;               // 1/sqrt(32)
    float sc = 0.f;
#pragma unroll
    for (int uu = 0; uu < 16; uu++) sc += xin[node * MULC + uu] * sWsc[uu * 32 + lane];
    q0 += sc * 0.25f;                         // inv_in
    sQ[warp][lane] = q0;
    __syncwarp();

    float* op = out + (size_t)node * 512;
#pragma unroll
    for (int t = lane; t < 512; t += 32) op[t] = sQ[warp][t];
}

extern "C" void kernel_launch(void* const* d_in, const int* in_sizes, int n_in,
                              void* d_out, int out_size) {
    const float* x     = (const float*)d_in[0];
    const float* pos   = (const float*)d_in[1];
    const float* Wpre  = (const float*)d_in[2];
    const float* Wpost = (const float*)d_in[3];
    const float* Wsc   = (const float*)d_in[4];
    const int*   send  = (const int*)d_in[5];
    const int*   recv  = (const int*)d_in[6];
    float*       out   = (float*)d_out;

    int n  = in_sizes[0] / MULC;  // 32768 nodes
    int e  = in_sizes[5];         // 1048576 edges
    int e4 = e / 4;

    k_prep<<<(n + 255) / 256, 256>>>(pos, Wpre, Wpost, n);
    k_hist<<<(e4 + 255) / 256, 256>>>((const int4*)recv, e4);
    k_scan1<<<128, 256>>>();
    k_scan2<<<1, 128>>>();
    k_scan3<<<128, 256>>>(n, e);
    k_scatter<<<(e4 + 255) / 256, 256>>>((const int4*)send, (const int4*)recv, e4);
    k_main<<<n / 8, 256>>>(x, Wpre, Wpost, Wsc, out, n);
}

// round 6
// speedup vs baseline: 1.9412x; 1.0478x over previous
#include <cuda_runtime.h>
#include <math.h>

#define NN   32768
#define EE   1048576
#define MULC 16
#define TMULC 32

// ---- scratch (static device globals; no allocation allowed) ----
__device__ int    d_count[NN];
__device__ int    d_offsets[NN + 1];
__device__ int    d_cursor[NN];
__device__ int    d_sorted[EE];       // sender id per edge, grouped by receiver
__device__ float4 d_pos4[NN];
__device__ float  d_Weff[3 * 16 * 32];
__device__ int    d_blocksum[128];
__device__ int    d_blockpref[128];

// -------- prep: zero histogram, pack positions, build W_eff ------------
__global__ void k_prep(const float* __restrict__ pos,
                       const float* __restrict__ Wpre,
                       const float* __restrict__ Wpost, int n) {
    int i = blockIdx.x * blockDim.x + threadIdx.x;
    if (i < n) {
        d_count[i] = 0;
        d_pos4[i] = make_float4(pos[3 * i], pos[3 * i + 1], pos[3 * i + 2], 0.f);
    }
    if (i < 3 * 16 * 32) {
        int ll = i >> 9;          // 0..2  -> irreps l = ll+1
        int u  = (i >> 5) & 15;
        int w  = i & 31;
        const float* A = Wpre  + (ll + 1) * MULC * TMULC + u * TMULC;
        const float* B = Wpost + (ll + 1) * TMULC * TMULC + w;
        float s = 0.f;
#pragma unroll
        for (int v = 0; v < TMULC; v++) s += A[v] * B[v * TMULC];
        d_Weff[i] = s;
    }
}

// ---------------- histogram of receivers (4 edges/thread) ---------------
__global__ void k_hist(const int4* __restrict__ recv4, int e4) {
    int i = blockIdx.x * blockDim.x + threadIdx.x;
    if (i < e4) {
        int4 r = recv4[i];
        atomicAdd(&d_count[r.x], 1);
        atomicAdd(&d_count[r.y], 1);
        atomicAdd(&d_count[r.z], 1);
        atomicAdd(&d_count[r.w], 1);
    }
}

// ------------- scan stage 1: per-block exclusive scan -------------------
__global__ void __launch_bounds__(256) k_scan1() {
    __shared__ int sh[256];
    int tid = threadIdx.x;
    int i   = blockIdx.x * 256 + tid;
    int v   = d_count[i];
    sh[tid] = v;
    __syncthreads();
#pragma unroll
    for (int off = 1; off < 256; off <<= 1) {
        int a = (tid >= off) ? sh[tid - off] : 0;
        __syncthreads();
        sh[tid] += a;
        __syncthreads();
    }
    d_offsets[i] = sh[tid] - v;           // partial (block-local) exclusive
    if (tid == 255) d_blocksum[blockIdx.x] = sh[255];
}

// ------------- scan stage 2: scan the 128 block sums --------------------
__global__ void __launch_bounds__(128) k_scan2() {
    __shared__ int sh[128];
    int tid = threadIdx.x;
    int v   = d_blocksum[tid];
    sh[tid] = v;
    __syncthreads();
#pragma unroll
    for (int off = 1; off < 128; off <<= 1) {
        int a = (tid >= off) ? sh[tid - off] : 0;
        __syncthreads();
        sh[tid] += a;
        __syncthreads();
    }
    d_blockpref[tid] = sh[tid] - v;
}

// ------------- scan stage 3: fixup + init cursor ------------------------
__global__ void __launch_bounds__(256) k_scan3(int n, int e) {
    int tid = threadIdx.x;
    int i   = blockIdx.x * 256 + tid;
    int o   = d_offsets[i] + d_blockpref[blockIdx.x];
    d_offsets[i] = o;
    d_cursor[i]  = o;
    if (i == 0) d_offsets[n] = e;
}

// -------- scatter sender ids into receiver-grouped order (4/thread) -----
__global__ void k_scatter(const int4* __restrict__ send4, const int4* __restrict__ recv4, int e4) {
    int i = blockIdx.x * blockDim.x + threadIdx.x;
    if (i < e4) {
        int4 s = send4[i];
        int4 r = recv4[i];
        d_sorted[atomicAdd(&d_cursor[r.x], 1)] = s.x;
        d_sorted[atomicAdd(&d_cursor[r.y], 1)] = s.y;
        d_sorted[atomicAdd(&d_cursor[r.z], 1)] = s.z;
        d_sorted[atomicAdd(&d_cursor[r.w], 1)] = s.w;
    }
}

// ---------------- main: per-node aggregation + fused node update --------
// One warp per node. Lane = (h = lane>>4, u = lane&15). Each round, half h
// processes edge 2k+h: no divergence; lane accumulates all 16 raw monomials.
__global__ void __launch_bounds__(256)
k_main(const float* __restrict__ xin,
       const float* __restrict__ Wpre,
       const float* __restrict__ Wpost,
       const float* __restrict__ Wsc,
       float* __restrict__ out, int n) {
    __shared__ float sWeff[3 * 16 * 32];
    __shared__ float sWpre0[16 * 32];
    __shared__ float sWpost0[32 * 32];
    __shared__ float sWsc[16 * 32];
    __shared__ __align__(16) float sA[8][16 * 20];  // [u][comp] stride 20 (80B = 5x16B)
    __shared__ float sQ[8][512];       // per-warp staged output row
    __shared__ float sP0[8][32];       // per-warp gelu intermediate

    int tid  = threadIdx.x;
    int warp = tid >> 5;
    int lane = tid & 31;
    int node = blockIdx.x * 8 + warp;
    int u    = lane & 15;
    int h    = lane >> 4;

    // --- issue the long-latency per-node loads BEFORE weight staging ----
    int nodeC = (node < n) ? node : (n - 1);
    int    beg = d_offsets[nodeC];
    int    end = d_offsets[nodeC + 1];
    float4 rp  = d_pos4[nodeC];
    int myE0   = beg + lane;
    int sid    = (myE0 < end) ? d_sorted[myE0] : 0;   // first tile prefetch

    for (int t = tid; t < 3 * 16 * 32; t += 256) sWeff[t]  = d_Weff[t];
    for (int t = tid; t < 16 * 32;    t += 256) sWpre0[t] = Wpre[t];
    for (int t = tid; t < 32 * 32;    t += 256) sWpost0[t] = Wpost[t];
    for (int t = tid; t < 16 * 32;    t += 256) sWsc[t]   = Wsc[t];
    __syncthreads();
    if (node >= n) return;

    // acc[c]: raw monomial aggregates for this lane's u, half-h edges only.
    // c: 0=1 1=X 2=Y 3=Z 4=XY 5=YZ 6=ZZ 7=XZ
    //    8=P 9=YP 10=XP 11=Y*ZZ 12=X*ZZ 13=Z*ZZ 14=ZP 15=XYZ   (P=X^2-Y^2)
    float acc[16];
#pragma unroll
    for (int c = 0; c < 16; c++) acc[c] = 0.f;

    for (int t0 = beg; t0 < end; t0 += 32) {
        // prefetch next tile's sender ids while we compute this tile
        int nt  = t0 + 32;
        int nxt = 0;
        if (nt < end) {
            int e2 = nt + lane;
            nxt = (e2 < end) ? d_sorted[e2] : 0;
        }
        int cnt = end - t0;
        if (cnt > 32) cnt = 32;
        int rounds = (cnt + 1) >> 1;
#pragma unroll 2
        for (int k = 0; k < rounds; k++) {
            int    ei = 2 * k + h;
            int    s  = __shfl_sync(0xffffffffu, sid, ei);
            float4 sp = d_pos4[s];
            float  xv = (ei < cnt) ? xin[s * MULC + u] : 0.f;
            float rx = rp.x - sp.x, ry = rp.y - sp.y, rz = rp.z - sp.z;
            float n2 = rx * rx + ry * ry + rz * rz;
            float iv = (n2 > 0.f) ? rsqrtf(n2) : 0.f;
            float X = rx * iv, Y = ry * iv, Z = rz * iv;
            float XY = X * Y, YZ = Y * Z, ZZ = Z * Z, XZ = X * Z;
            float P  = fmaf(X, X, -(Y * Y));
            acc[0] += xv;
            acc[1] = fmaf(xv, X, acc[1]);
            acc[2] = fmaf(xv, Y, acc[2]);
            acc[3] = fmaf(xv, Z, acc[3]);
            acc[4] = fmaf(xv, XY, acc[4]);
            acc[5] = fmaf(xv, YZ, acc[5]);
            acc[6] = fmaf(xv, ZZ, acc[6]);
            acc[7] = fmaf(xv, XZ, acc[7]);
            acc[8]  = fmaf(xv, P, acc[8]);
            acc[9]  = fmaf(xv, Y * P, acc[9]);
            acc[10] = fmaf(xv, X * P, acc[10]);
            acc[11] = fmaf(xv, YZ * Z, acc[11]);
            acc[12] = fmaf(xv, XZ * Z, acc[12]);
            acc[13] = fmaf(xv, Z * ZZ, acc[13]);
            acc[14] = fmaf(xv, Z * P, acc[14]);
            acc[15] = fmaf(xv, XY * Z, acc[15]);
        }
        sid = nxt;
    }

    // merge the two half-edge partial sums (lanes u and u+16 both end full)
#pragma unroll
    for (int c = 0; c < 16; c++) acc[c] += __shfl_xor_sync(0xffffffffu, acc[c], 16);

    // ---- reconstruct normalized SH aggregates; lane (u,h) emits comps h*8.. ----
    float ys[8];
    if (h == 0) {
        ys[0] = acc[0];
        ys[1] = 1.7320508075688772f * acc[1];
        ys[2] = 1.7320508075688772f * acc[2];
        ys[3] = 1.7320508075688772f * acc[3];
        ys[4] = 3.872983346207417f * acc[4];
        ys[5] = 3.872983346207417f * acc[5];
        ys[6] = 1.118033988749895f * (3.f * acc[6] - acc[0]);          // 0.5*sqrt(5)
        ys[7] = 3.872983346207417f * acc[7];
    } else {
        ys[0] = 1.9364916731037085f * acc[8];                          // 0.5*sqrt(15)
        ys[1] = 2.091650066335189f * (acc[2] - acc[11] + 2.f * acc[9]); // y(3xx-yy)
        ys[2] = 10.246950765959598f * acc[15];                         // sqrt(105)
        ys[3] = 1.6201851746019651f * (5.f * acc[11] - acc[2]);        // sqrt(21/8)
        ys[4] = 1.3228756555322954f * (5.f * acc[13] - 3.f * acc[3]);  // 0.5*sqrt(7)
        ys[5] = 1.6201851746019651f * (5.f * acc[12] - acc[1]);
        ys[6] = 5.123475382979799f * acc[14];                          // 0.5*sqrt(105)
        ys[7] = 2.091650066335189f * (2.f * acc[10] + acc[12] - acc[1]); // x(xx-3yy)
    }
    // two STS.128 per lane (aligned: (u*20+h*8)*4 bytes is 16B-multiple)
    {
        float4* dst = reinterpret_cast<float4*>(&sA[warp][u * 20 + h * 8]);
        dst[0] = make_float4(ys[0], ys[1], ys[2], ys[3]);
        dst[1] = make_float4(ys[4], ys[5], ys[6], ys[7]);
    }
    __syncwarp();

    // ----- node update: r[i] = sum_u sA[u][i] * W(i-block)[u][lane] -----
    float r[16];
#pragma unroll
    for (int i = 0; i < 16; i++) r[i] = 0.f;
#pragma unroll
    for (int uu = 0; uu < 16; uu++) {
        const float4* base = reinterpret_cast<const float4*>(&sA[warp][uu * 20]);
        float4 A0 = base[0];   // comps 0..3
        float4 A1 = base[1];   // comps 4..7
        float4 A2 = base[2];   // comps 8..11
        float4 A3 = base[3];   // comps 12..15
        float wp = sWpre0[uu * 32 + lane];
        float w1 = sWeff[(0 * 16 + uu) * 32 + lane];
        float w2 = sWeff[(1 * 16 + uu) * 32 + lane];
        float w3 = sWeff[(2 * 16 + uu) * 32 + lane];
        r[0]  = fmaf(A0.x, wp, r[0]);
        r[1]  = fmaf(A0.y, w1, r[1]);
        r[2]  = fmaf(A0.z, w1, r[2]);
        r[3]  = fmaf(A0.w, w1, r[3]);
        r[4]  = fmaf(A1.x, w2, r[4]);
        r[5]  = fmaf(A1.y, w2, r[5]);
        r[6]  = fmaf(A1.z, w2, r[6]);
        r[7]  = fmaf(A1.w, w2, r[7]);
        r[8]  = fmaf(A2.x, w2, r[8]);
        r[9]  = fmaf(A2.y, w3, r[9]);
        r[10] = fmaf(A2.z, w3, r[10]);
        r[11] = fmaf(A2.w, w3, r[11]);
        r[12] = fmaf(A3.x, w3, r[12]);
        r[13] = fmaf(A3.y, w3, r[13]);
        r[14] = fmaf(A3.z, w3, r[14]);
        r[15] = fmaf(A3.w, w3, r[15]);
    }

    const float SCALE_L = 1.0f / (128.0f * 5.656854249492381f); // 1/(DENOM*sqrt(mul)*sqrt(tmul))
    // stage l>=1 outputs
#pragma unroll
    for (int j = 0; j < 3; j++) sQ[warp][32  + lane * 3 + j] = r[1 + j] * SCALE_L;
#pragma unroll
    for (int j = 0; j < 5; j++) sQ[warp][128 + lane * 5 + j] = r[4 + j] * SCALE_L;
#pragma unroll
    for (int j = 0; j < 7; j++) sQ[warp][288 + lane * 7 + j] = r[9 + j] * SCALE_L;

    // l = 0 path: pre -> gelu -> post, + shortcut
    float p = r[0] * (1.f / 128.f);           // /DENOM * inv_in
    // exact gelu * C_GELU, C = (E[gelu(z)^2])^{-1/2} = 1.5335285
    p = 1.5335285f * 0.5f * p * (1.f + erff(p * 0.7071067811865476f));
    sP0[warp][lane] = p;
    __syncwarp();
    float q0 = 0.f;
#pragma unroll
    for (int v = 0; v < 32; v++) q0 += sP0[warp][v] * sWpost0[v * 32 + lane];
    q0 *= 0.17677669529663687f;               // 1/sqrt(32)
    float sc = 0.f;
#pragma unroll
    for (int uu = 0; uu < 16; uu++) sc += xin[node * MULC + uu] * sWsc[uu * 32 + lane];
    q0 += sc * 0.25f;                         // inv_in
    sQ[warp][lane] = q0;
    __syncwarp();

    float* op = out + (size_t)node * 512;
#pragma unroll
    for (int t = lane; t < 512; t += 32) op[t] = sQ[warp][t];
}

extern "C" void kernel_launch(void* const* d_in, const int* in_sizes, int n_in,
                              void* d_out, int out_size) {
    const float* x     = (const float*)d_in[0];
    const float* pos   = (const float*)d_in[1];
    const float* Wpre  = (const float*)d_in[2];
    const float* Wpost = (const float*)d_in[3];
    const float* Wsc   = (const float*)d_in[4];
    const int*   send  = (const int*)d_in[5];
    const int*   recv  = (const int*)d_in[6];
    float*       out   = (float*)d_out;

    int n  = in_sizes[0] / MULC;  // 32768 nodes
    int e  = in_sizes[5];         // 1048576 edges
    int e4 = e / 4;

    k_prep<<<(n + 255) / 256, 256>>>(pos, Wpre, Wpost, n);
    k_hist<<<(e4 + 255) / 256, 256>>>((const int4*)recv, e4);
    k_scan1<<<128, 256>>>();
    k_scan2<<<1, 128>>>();
    k_scan3<<<128, 256>>>(n, e);
    k_scatter<<<(e4 + 255) / 256, 256>>>((const int4*)send, (const int4*)recv, e4);
    k_main<<<n / 8, 256>>>(x, Wpre, Wpost, Wsc, out, n);
}

// round 7
// speedup vs baseline: 2.1880x; 1.1271x over previous
#include <cuda_runtime.h>
#include <math.h>

#define NN   32768
#define EE   1048576
#define MULC 16
#define TMULC 32

// ---- scratch (static device globals; no allocation allowed) ----
// INVARIANT: d_count is all-zero at entry to each kernel_launch call.
// (Zero at module load; k_scan1 re-zeroes it after consuming the counts.)
__device__ int    d_count[NN];
__device__ int    d_offsets[NN + 1];
__device__ int    d_cursor[NN];
__device__ int    d_sorted[EE];       // sender id per edge, grouped by receiver
__device__ float4 d_pos4[NN];
__device__ __align__(16) float d_Weff[3 * 16 * 32];
__device__ int    d_blocksum[128];
__device__ int    d_blockpref[128];

// -------- pre: histogram + pack positions + build W_eff (one kernel) ----
__global__ void k_pre(const float* __restrict__ pos,
                      const float* __restrict__ Wpre,
                      const float* __restrict__ Wpost,
                      const int4* __restrict__ recv4,
                      int n, int e4) {
    int i = blockIdx.x * blockDim.x + threadIdx.x;
    if (i < e4) {
        int4 r = recv4[i];
        atomicAdd(&d_count[r.x], 1);
        atomicAdd(&d_count[r.y], 1);
        atomicAdd(&d_count[r.z], 1);
        atomicAdd(&d_count[r.w], 1);
    }
    if (i < n) {
        d_pos4[i] = make_float4(pos[3 * i], pos[3 * i + 1], pos[3 * i + 2], 0.f);
    }
    if (i < 3 * 16 * 32) {
        int ll = i >> 9;          // 0..2  -> irreps l = ll+1
        int u  = (i >> 5) & 15;
        int w  = i & 31;
        const float* A = Wpre  + (ll + 1) * MULC * TMULC + u * TMULC;
        const float* B = Wpost + (ll + 1) * TMULC * TMULC + w;
        float s = 0.f;
#pragma unroll
        for (int v = 0; v < TMULC; v++) s += A[v] * B[v * TMULC];
        d_Weff[i] = s;
    }
}

// ------------- scan stage 1: per-block exclusive scan (+re-zero) --------
__global__ void __launch_bounds__(256) k_scan1() {
    __shared__ int sh[256];
    int tid = threadIdx.x;
    int i   = blockIdx.x * 256 + tid;
    int v   = d_count[i];
    d_count[i] = 0;                       // restore invariant for next call
    sh[tid] = v;
    __syncthreads();
#pragma unroll
    for (int off = 1; off < 256; off <<= 1) {
        int a = (tid >= off) ? sh[tid - off] : 0;
        __syncthreads();
        sh[tid] += a;
        __syncthreads();
    }
    d_offsets[i] = sh[tid] - v;           // partial (block-local) exclusive
    if (tid == 255) d_blocksum[blockIdx.x] = sh[255];
}

// ------------- scan stage 2: scan the 128 block sums --------------------
__global__ void __launch_bounds__(128) k_scan2() {
    __shared__ int sh[128];
    int tid = threadIdx.x;
    int v   = d_blocksum[tid];
    sh[tid] = v;
    __syncthreads();
#pragma unroll
    for (int off = 1; off < 128; off <<= 1) {
        int a = (tid >= off) ? sh[tid - off] : 0;
        __syncthreads();
        sh[tid] += a;
        __syncthreads();
    }
    d_blockpref[tid] = sh[tid] - v;
}

// ------------- scan stage 3: fixup + init cursor ------------------------
__global__ void __launch_bounds__(256) k_scan3(int n, int e) {
    int tid = threadIdx.x;
    int i   = blockIdx.x * 256 + tid;
    int o   = d_offsets[i] + d_blockpref[blockIdx.x];
    d_offsets[i] = o;
    d_cursor[i]  = o;
    if (i == 0) d_offsets[n] = e;
}

// -------- scatter sender ids into receiver-grouped order (4/thread) -----
__global__ void k_scatter(const int4* __restrict__ send4, const int4* __restrict__ recv4, int e4) {
    int i = blockIdx.x * blockDim.x + threadIdx.x;
    if (i < e4) {
        int4 s = send4[i];
        int4 r = recv4[i];
        d_sorted[atomicAdd(&d_cursor[r.x], 1)] = s.x;
        d_sorted[atomicAdd(&d_cursor[r.y], 1)] = s.y;
        d_sorted[atomicAdd(&d_cursor[r.z], 1)] = s.z;
        d_sorted[atomicAdd(&d_cursor[r.w], 1)] = s.w;
    }
}

// ---------------- main: per-node aggregation + fused node update --------
// One warp per node. Lane = (h = lane>>4, u = lane&15). Each round, half h
// processes edge 2k+h: no divergence; lane accumulates all 16 raw monomials.
__global__ void __launch_bounds__(256)
k_main(const float* __restrict__ xin,
       const float* __restrict__ Wpre,
       const float* __restrict__ Wpost,
       const float* __restrict__ Wsc,
       float* __restrict__ out, int n) {
    __shared__ __align__(16) float sWeff[3 * 16 * 32];
    __shared__ __align__(16) float sWpre0[16 * 32];
    __shared__ __align__(16) float sWpost0[32 * 32];
    __shared__ __align__(16) float sWsc[16 * 32];
    __shared__ __align__(16) float sA[8][16 * 20];  // [u][comp] stride 20 (80B)
    __shared__ __align__(16) float sQ[8][512];      // per-warp staged output row
    __shared__ float sP0[8][32];                    // per-warp gelu intermediate

    int tid  = threadIdx.x;
    int warp = tid >> 5;
    int lane = tid & 31;
    int node = blockIdx.x * 8 + warp;
    int u    = lane & 15;
    int h    = lane >> 4;

    // --- issue the long-latency per-node loads BEFORE weight staging ----
    int nodeC = (node < n) ? node : (n - 1);
    int    beg = d_offsets[nodeC];
    int    end = d_offsets[nodeC + 1];
    float4 rp  = d_pos4[nodeC];
    int myE0   = beg + lane;
    int sid    = (myE0 < end) ? d_sorted[myE0] : 0;   // first tile prefetch

    // vectorized weight staging (float4)
    {
        const float4* W4;
        float4* S4;
        W4 = reinterpret_cast<const float4*>(d_Weff);
        S4 = reinterpret_cast<float4*>(sWeff);
        for (int t = tid; t < 384; t += 256) S4[t] = W4[t];
        W4 = reinterpret_cast<const float4*>(Wpre);
        S4 = reinterpret_cast<float4*>(sWpre0);
        for (int t = tid; t < 128; t += 256) S4[t] = W4[t];
        W4 = reinterpret_cast<const float4*>(Wpost);
        S4 = reinterpret_cast<float4*>(sWpost0);
        for (int t = tid; t < 256; t += 256) S4[t] = W4[t];
        W4 = reinterpret_cast<const float4*>(Wsc);
        S4 = reinterpret_cast<float4*>(sWsc);
        for (int t = tid; t < 128; t += 256) S4[t] = W4[t];
    }
    __syncthreads();
    if (node >= n) return;

    // acc[c]: raw monomial aggregates for this lane's u, half-h edges only.
    // c: 0=1 1=X 2=Y 3=Z 4=XY 5=YZ 6=ZZ 7=XZ
    //    8=P 9=YP 10=XP 11=Y*ZZ 12=X*ZZ 13=Z*ZZ 14=ZP 15=XYZ   (P=X^2-Y^2)
    float acc[16];
#pragma unroll
    for (int c = 0; c < 16; c++) acc[c] = 0.f;

    for (int t0 = beg; t0 < end; t0 += 32) {
        // prefetch next tile's sender ids while we compute this tile
        int nt  = t0 + 32;
        int nxt = 0;
        if (nt < end) {
            int e2 = nt + lane;
            nxt = (e2 < end) ? d_sorted[e2] : 0;
        }
        int cnt = end - t0;
        if (cnt > 32) cnt = 32;
        int rounds = (cnt + 1) >> 1;
#pragma unroll 2
        for (int k = 0; k < rounds; k++) {
            int    ei = 2 * k + h;
            int    s  = __shfl_sync(0xffffffffu, sid, ei);
            float4 sp = d_pos4[s];
            float  xv = (ei < cnt) ? xin[s * MULC + u] : 0.f;
            float rx = rp.x - sp.x, ry = rp.y - sp.y, rz = rp.z - sp.z;
            float n2 = rx * rx + ry * ry + rz * rz;
            float iv = (n2 > 0.f) ? rsqrtf(n2) : 0.f;
            float X = rx * iv, Y = ry * iv, Z = rz * iv;
            float XY = X * Y, YZ = Y * Z, ZZ = Z * Z, XZ = X * Z;
            float P  = fmaf(X, X, -(Y * Y));
            acc[0] += xv;
            acc[1] = fmaf(xv, X, acc[1]);
            acc[2] = fmaf(xv, Y, acc[2]);
            acc[3] = fmaf(xv, Z, acc[3]);
            acc[4] = fmaf(xv, XY, acc[4]);
            acc[5] = fmaf(xv, YZ, acc[5]);
            acc[6] = fmaf(xv, ZZ, acc[6]);
            acc[7] = fmaf(xv, XZ, acc[7]);
            acc[8]  = fmaf(xv, P, acc[8]);
            acc[9]  = fmaf(xv, Y * P, acc[9]);
            acc[10] = fmaf(xv, X * P, acc[10]);
            acc[11] = fmaf(xv, YZ * Z, acc[11]);
            acc[12] = fmaf(xv, XZ * Z, acc[12]);
            acc[13] = fmaf(xv, Z * ZZ, acc[13]);
            acc[14] = fmaf(xv, Z * P, acc[14]);
            acc[15] = fmaf(xv, XY * Z, acc[15]);
        }
        sid = nxt;
    }

    // merge the two half-edge partial sums (lanes u and u+16 both end full)
#pragma unroll
    for (int c = 0; c < 16; c++) acc[c] += __shfl_xor_sync(0xffffffffu, acc[c], 16);

    // ---- reconstruct normalized SH aggregates; lane (u,h) emits comps h*8.. ----
    float ys[8];
    if (h == 0) {
        ys[0] = acc[0];
        ys[1] = 1.7320508075688772f * acc[1];
        ys[2] = 1.7320508075688772f * acc[2];
        ys[3] = 1.7320508075688772f * acc[3];
        ys[4] = 3.872983346207417f * acc[4];
        ys[5] = 3.872983346207417f * acc[5];
        ys[6] = 1.118033988749895f * (3.f * acc[6] - acc[0]);          // 0.5*sqrt(5)
        ys[7] = 3.872983346207417f * acc[7];
    } else {
        ys[0] = 1.9364916731037085f * acc[8];                          // 0.5*sqrt(15)
        ys[1] = 2.091650066335189f * (acc[2] - acc[11] + 2.f * acc[9]); // y(3xx-yy)
        ys[2] = 10.246950765959598f * acc[15];                         // sqrt(105)
        ys[3] = 1.6201851746019651f * (5.f * acc[11] - acc[2]);        // sqrt(21/8)
        ys[4] = 1.3228756555322954f * (5.f * acc[13] - 3.f * acc[3]);  // 0.5*sqrt(7)
        ys[5] = 1.6201851746019651f * (5.f * acc[12] - acc[1]);
        ys[6] = 5.123475382979799f * acc[14];                          // 0.5*sqrt(105)
        ys[7] = 2.091650066335189f * (2.f * acc[10] + acc[12] - acc[1]); // x(xx-3yy)
    }
    // two STS.128 per lane (aligned: (u*20+h*8)*4 bytes is 16B-multiple)
    {
        float4* dst = reinterpret_cast<float4*>(&sA[warp][u * 20 + h * 8]);
        dst[0] = make_float4(ys[0], ys[1], ys[2], ys[3]);
        dst[1] = make_float4(ys[4], ys[5], ys[6], ys[7]);
    }
    __syncwarp();

    // ----- node update: r[i] = sum_u sA[u][i] * W(i-block)[u][lane] -----
    float r[16];
#pragma unroll
    for (int i = 0; i < 16; i++) r[i] = 0.f;
#pragma unroll
    for (int uu = 0; uu < 16; uu++) {
        const float4* base = reinterpret_cast<const float4*>(&sA[warp][uu * 20]);
        float4 A0 = base[0];   // comps 0..3
        float4 A1 = base[1];   // comps 4..7
        float4 A2 = base[2];   // comps 8..11
        float4 A3 = base[3];   // comps 12..15
        float wp = sWpre0[uu * 32 + lane];
        float w1 = sWeff[(0 * 16 + uu) * 32 + lane];
        float w2 = sWeff[(1 * 16 + uu) * 32 + lane];
        float w3 = sWeff[(2 * 16 + uu) * 32 + lane];
        r[0]  = fmaf(A0.x, wp, r[0]);
        r[1]  = fmaf(A0.y, w1, r[1]);
        r[2]  = fmaf(A0.z, w1, r[2]);
        r[3]  = fmaf(A0.w, w1, r[3]);
        r[4]  = fmaf(A1.x, w2, r[4]);
        r[5]  = fmaf(A1.y, w2, r[5]);
        r[6]  = fmaf(A1.z, w2, r[6]);
        r[7]  = fmaf(A1.w, w2, r[7]);
        r[8]  = fmaf(A2.x, w2, r[8]);
        r[9]  = fmaf(A2.y, w3, r[9]);
        r[10] = fmaf(A2.z, w3, r[10]);
        r[11] = fmaf(A2.w, w3, r[11]);
        r[12] = fmaf(A3.x, w3, r[12]);
        r[13] = fmaf(A3.y, w3, r[13]);
        r[14] = fmaf(A3.z, w3, r[14]);
        r[15] = fmaf(A3.w, w3, r[15]);
    }

    const float SCALE_L = 1.0f / (128.0f * 5.656854249492381f); // 1/(DENOM*sqrt(mul)*sqrt(tmul))
    // stage l>=1 outputs
#pragma unroll
    for (int j = 0; j < 3; j++) sQ[warp][32  + lane * 3 + j] = r[1 + j] * SCALE_L;
#pragma unroll
    for (int j = 0; j < 5; j++) sQ[warp][128 + lane * 5 + j] = r[4 + j] * SCALE_L;
#pragma unroll
    for (int j = 0; j < 7; j++) sQ[warp][288 + lane * 7 + j] = r[9 + j] * SCALE_L;

    // l = 0 path: pre -> gelu -> post, + shortcut
    float p = r[0] * (1.f / 128.f);           // /DENOM * inv_in
    // exact gelu * C_GELU, C = (E[gelu(z)^2])^{-1/2} = 1.5335285
    p = 1.5335285f * 0.5f * p * (1.f + erff(p * 0.7071067811865476f));
    sP0[warp][lane] = p;
    __syncwarp();
    float q0 = 0.f;
#pragma unroll
    for (int v = 0; v < 32; v++) q0 += sP0[warp][v] * sWpost0[v * 32 + lane];
    q0 *= 0.17677669529663687f;               // 1/sqrt(32)
    // shortcut: 4 x LDG.128 broadcast of this node's x row
    float sc = 0.f;
    {
        const float4* xr = reinterpret_cast<const float4*>(xin + (size_t)node * MULC);
#pragma unroll
        for (int g = 0; g < 4; g++) {
            float4 xg = xr[g];
            sc = fmaf(xg.x, sWsc[(g * 4 + 0) * 32 + lane], sc);
            sc = fmaf(xg.y, sWsc[(g * 4 + 1) * 32 + lane], sc);
            sc = fmaf(xg.z, sWsc[(g * 4 + 2) * 32 + lane], sc);
            sc = fmaf(xg.w, sWsc[(g * 4 + 3) * 32 + lane], sc);
        }
    }
    q0 += sc * 0.25f;                         // inv_in
    sQ[warp][lane] = q0;
    __syncwarp();

    // vectorized writeback: 4 x STG.128 per lane
    {
        float4*       op4 = reinterpret_cast<float4*>(out + (size_t)node * 512);
        const float4* sq4 = reinterpret_cast<const float4*>(sQ[warp]);
#pragma unroll
        for (int t = 0; t < 4; t++) op4[lane + 32 * t] = sq4[lane + 32 * t];
    }
}

extern "C" void kernel_launch(void* const* d_in, const int* in_sizes, int n_in,
                              void* d_out, int out_size) {
    const float* x     = (const float*)d_in[0];
    const float* pos   = (const float*)d_in[1];
    const float* Wpre  = (const float*)d_in[2];
    const float* Wpost = (const float*)d_in[3];
    const float* Wsc   = (const float*)d_in[4];
    const int*   send  = (const int*)d_in[5];
    const int*   recv  = (const int*)d_in[6];
    float*       out   = (float*)d_out;

    int n  = in_sizes[0] / MULC;  // 32768 nodes
    int e  = in_sizes[5];         // 1048576 edges
    int e4 = e / 4;

    k_pre<<<(e4 + 255) / 256, 256>>>(pos, Wpre, Wpost, (const int4*)recv, n, e4);
    k_scan1<<<128, 256>>>();
    k_scan2<<<1, 128>>>();
    k_scan3<<<128, 256>>>(n, e);
    k_scatter<<<(e4 + 255) / 256, 256>>>((const int4*)send, (const int4*)recv, e4);
    k_main<<<n / 8, 256>>>(x, Wpre, Wpost, Wsc, out, n);
}

// round 8
// speedup vs baseline: 2.2555x; 1.0308x over previous
#include <cuda_runtime.h>
#include <math.h>

#define NN   32768
#define EE   1048576
#define MULC 16
#define TMULC 32

// ---- scratch (static device globals; no allocation allowed) ----
// INVARIANT: d_count is all-zero at entry to each kernel_launch call.
// (Zero at module load; k_scan re-zeroes it after consuming the counts.)
__device__ int    d_count[NN];
__device__ int    d_offsets[NN + 1];
__device__ int    d_cursor[NN];
__device__ int    d_sorted[EE];       // sender id per edge, grouped by receiver
__device__ float4 d_pos4[NN];
__device__ __align__(16) float d_Weff[3 * 16 * 32];
__device__ int    d_blocksum[128];    // scan aggregates; -1 = not ready (armed by k_pre)

// -------- pre: histogram + pack positions + W_eff + arm scan sentinels --
__global__ void k_pre(const float* __restrict__ pos,
                      const float* __restrict__ Wpre,
                      const float* __restrict__ Wpost,
                      const int4* __restrict__ recv4,
                      int n, int e4) {
    int i = blockIdx.x * blockDim.x + threadIdx.x;
    if (i < e4) {
        int4 r = recv4[i];
        atomicAdd(&d_count[r.x], 1);
        atomicAdd(&d_count[r.y], 1);
        atomicAdd(&d_count[r.z], 1);
        atomicAdd(&d_count[r.w], 1);
    }
    if (i < n) {
        d_pos4[i] = make_float4(pos[3 * i], pos[3 * i + 1], pos[3 * i + 2], 0.f);
    }
    if (i < 128) d_blocksum[i] = -1;      // arm lookback sentinels
    if (i < 3 * 16 * 32) {
        int ll = i >> 9;          // 0..2  -> irreps l = ll+1
        int u  = (i >> 5) & 15;
        int w  = i & 31;
        const float* A = Wpre  + (ll + 1) * MULC * TMULC + u * TMULC;
        const float* B = Wpost + (ll + 1) * TMULC * TMULC + w;
        float s = 0.f;
#pragma unroll
        for (int v = 0; v < TMULC; v++) s += A[v] * B[v * TMULC];
        d_Weff[i] = s;
    }
}

// ------ single-kernel exclusive scan via decoupled lookback -------------
// 128 blocks x 256 threads, all resident simultaneously (128 < 148 SMs).
__global__ void __launch_bounds__(256) k_scan(int n, int e) {
    __shared__ int sh[256];
    __shared__ int spre[128];
    __shared__ int prefbase;
    int tid = threadIdx.x;
    int bid = blockIdx.x;
    int i   = bid * 256 + tid;
    int v   = d_count[i];
    d_count[i] = 0;                       // restore invariant for next call
    sh[tid] = v;
    __syncthreads();
#pragma unroll
    for (int off = 1; off < 256; off <<= 1) {
        int a = (tid >= off) ? sh[tid - off] : 0;
        __syncthreads();
        sh[tid] += a;
        __syncthreads();
    }
    int incl = sh[tid];                   // inclusive block-local prefix
    if (tid == 255) atomicExch(&d_blocksum[bid], incl);  // publish aggregate
    // lookback: thread t spins on predecessor t's aggregate
    if (tid < bid) {
        int vv;
        do { vv = atomicAdd(&d_blocksum[tid], 0); } while (vv < 0);
        spre[tid] = vv;
    }
    __syncthreads();
    if (tid == 0) {
        int s = 0;
        for (int t = 0; t < bid; t++) s += spre[t];
        prefbase = s;
    }
    __syncthreads();
    int o = prefbase + incl - v;          // global exclusive prefix
    d_offsets[i] = o;
    d_cursor[i]  = o;
    if (i == n - 1) d_offsets[n] = e;
}

// -------- scatter sender ids into receiver-grouped order (4/thread) -----
__global__ void k_scatter(const int4* __restrict__ send4, const int4* __restrict__ recv4, int e4) {
    int i = blockIdx.x * blockDim.x + threadIdx.x;
    if (i < e4) {
        int4 s = send4[i];
        int4 r = recv4[i];
        d_sorted[atomicAdd(&d_cursor[r.x], 1)] = s.x;
        d_sorted[atomicAdd(&d_cursor[r.y], 1)] = s.y;
        d_sorted[atomicAdd(&d_cursor[r.z], 1)] = s.z;
        d_sorted[atomicAdd(&d_cursor[r.w], 1)] = s.w;
    }
}

// ---------------- main: per-node aggregation + fused node update --------
// One warp per node. Lane = (h = lane>>4, u = lane&15). Each round, half h
// processes edge 2k+h: no divergence; lane accumulates all 16 raw monomials.
__global__ void __launch_bounds__(256)
k_main(const float* __restrict__ xin,
       const float* __restrict__ Wpre,
       const float* __restrict__ Wpost,
       const float* __restrict__ Wsc,
       float* __restrict__ out, int n) {
    __shared__ __align__(16) float sWeff[3 * 16 * 32];
    __shared__ __align__(16) float sWpre0[16 * 32];
    __shared__ __align__(16) float sWpost0[32 * 32];
    __shared__ __align__(16) float sWsc[16 * 32];
    __shared__ __align__(16) float sA[8][16 * 20];  // [u][comp] stride 20 (80B)
    __shared__ __align__(16) float sQ[8][512];      // per-warp staged output row
    __shared__ float sP0[8][32];                    // per-warp gelu intermediate

    int tid  = threadIdx.x;
    int warp = tid >> 5;
    int lane = tid & 31;
    int node = blockIdx.x * 8 + warp;
    int u    = lane & 15;
    int h    = lane >> 4;

    // --- issue the long-latency per-node loads BEFORE weight staging ----
    int nodeC = (node < n) ? node : (n - 1);
    int    beg = d_offsets[nodeC];
    int    end = d_offsets[nodeC + 1];
    float4 rp  = d_pos4[nodeC];
    int myE0   = beg + lane;
    int sid    = (myE0 < end) ? d_sorted[myE0] : 0;   // first tile prefetch

    // vectorized weight staging (float4)
    {
        const float4* W4;
        float4* S4;
        W4 = reinterpret_cast<const float4*>(d_Weff);
        S4 = reinterpret_cast<float4*>(sWeff);
        for (int t = tid; t < 384; t += 256) S4[t] = W4[t];
        W4 = reinterpret_cast<const float4*>(Wpre);
        S4 = reinterpret_cast<float4*>(sWpre0);
        for (int t = tid; t < 128; t += 256) S4[t] = W4[t];
        W4 = reinterpret_cast<const float4*>(Wpost);
        S4 = reinterpret_cast<float4*>(sWpost0);
        for (int t = tid; t < 256; t += 256) S4[t] = W4[t];
        W4 = reinterpret_cast<const float4*>(Wsc);
        S4 = reinterpret_cast<float4*>(sWsc);
        for (int t = tid; t < 128; t += 256) S4[t] = W4[t];
    }
    __syncthreads();
    if (node >= n) return;

    // acc[c]: raw monomial aggregates for this lane's u, half-h edges only.
    // c: 0=1 1=X 2=Y 3=Z 4=XY 5=YZ 6=ZZ 7=XZ
    //    8=P 9=YP 10=XP 11=Y*ZZ 12=X*ZZ 13=Z*ZZ 14=ZP 15=XYZ   (P=X^2-Y^2)
    float acc[16];
#pragma unroll
    for (int c = 0; c < 16; c++) acc[c] = 0.f;

    for (int t0 = beg; t0 < end; t0 += 32) {
        // prefetch next tile's sender ids while we compute this tile
        int nt  = t0 + 32;
        int nxt = 0;
        if (nt < end) {
            int e2 = nt + lane;
            nxt = (e2 < end) ? d_sorted[e2] : 0;
        }
        int cnt = end - t0;
        if (cnt > 32) cnt = 32;
        int rounds = (cnt + 1) >> 1;
#pragma unroll 2
        for (int k = 0; k < rounds; k++) {
            int    ei = 2 * k + h;
            int    s  = __shfl_sync(0xffffffffu, sid, ei);
            float4 sp = d_pos4[s];
            float  xv = (ei < cnt) ? xin[s * MULC + u] : 0.f;
            float rx = rp.x - sp.x, ry = rp.y - sp.y, rz = rp.z - sp.z;
            float n2 = rx * rx + ry * ry + rz * rz;
            float iv = (n2 > 0.f) ? rsqrtf(n2) : 0.f;
            float X = rx * iv, Y = ry * iv, Z = rz * iv;
            float XY = X * Y, YZ = Y * Z, ZZ = Z * Z, XZ = X * Z;
            float P  = fmaf(X, X, -(Y * Y));
            acc[0] += xv;
            acc[1] = fmaf(xv, X, acc[1]);
            acc[2] = fmaf(xv, Y, acc[2]);
            acc[3] = fmaf(xv, Z, acc[3]);
            acc[4] = fmaf(xv, XY, acc[4]);
            acc[5] = fmaf(xv, YZ, acc[5]);
            acc[6] = fmaf(xv, ZZ, acc[6]);
            acc[7] = fmaf(xv, XZ, acc[7]);
            acc[8]  = fmaf(xv, P, acc[8]);
            acc[9]  = fmaf(xv, Y * P, acc[9]);
            acc[10] = fmaf(xv, X * P, acc[10]);
            acc[11] = fmaf(xv, YZ * Z, acc[11]);
            acc[12] = fmaf(xv, XZ * Z, acc[12]);
            acc[13] = fmaf(xv, Z * ZZ, acc[13]);
            acc[14] = fmaf(xv, Z * P, acc[14]);
            acc[15] = fmaf(xv, XY * Z, acc[15]);
        }
        sid = nxt;
    }

    // merge the two half-edge partial sums (lanes u and u+16 both end full)
#pragma unroll
    for (int c = 0; c < 16; c++) acc[c] += __shfl_xor_sync(0xffffffffu, acc[c], 16);

    // ---- reconstruct normalized SH aggregates; lane (u,h) emits comps h*8.. ----
    float ys[8];
    if (h == 0) {
        ys[0] = acc[0];
        ys[1] = 1.7320508075688772f * acc[1];
        ys[2] = 1.7320508075688772f * acc[2];
        ys[3] = 1.7320508075688772f * acc[3];
        ys[4] = 3.872983346207417f * acc[4];
        ys[5] = 3.872983346207417f * acc[5];
        ys[6] = 1.118033988749895f * (3.f * acc[6] - acc[0]);          // 0.5*sqrt(5)
        ys[7] = 3.872983346207417f * acc[7];
    } else {
        ys[0] = 1.9364916731037085f * acc[8];                          // 0.5*sqrt(15)
        ys[1] = 2.091650066335189f * (acc[2] - acc[11] + 2.f * acc[9]); // y(3xx-yy)
        ys[2] = 10.246950765959598f * acc[15];                         // sqrt(105)
        ys[3] = 1.6201851746019651f * (5.f * acc[11] - acc[2]);        // sqrt(21/8)
        ys[4] = 1.3228756555322954f * (5.f * acc[13] - 3.f * acc[3]);  // 0.5*sqrt(7)
        ys[5] = 1.6201851746019651f * (5.f * acc[12] - acc[1]);
        ys[6] = 5.123475382979799f * acc[14];                          // 0.5*sqrt(105)
        ys[7] = 2.091650066335189f * (2.f * acc[10] + acc[12] - acc[1]); // x(xx-3yy)
    }
    // two STS.128 per lane (aligned: (u*20+h*8)*4 bytes is 16B-multiple)
    {
        float4* dst = reinterpret_cast<float4*>(&sA[warp][u * 20 + h * 8]);
        dst[0] = make_float4(ys[0], ys[1], ys[2], ys[3]);
        dst[1] = make_float4(ys[4], ys[5], ys[6], ys[7]);
    }
    __syncwarp();

    // ----- node update: r[i] = sum_u sA[u][i] * W(i-block)[u][lane] -----
    float r[16];
#pragma unroll
    for (int i = 0; i < 16; i++) r[i] = 0.f;
#pragma unroll
    for (int uu = 0; uu < 16; uu++) {
        const float4* base = reinterpret_cast<const float4*>(&sA[warp][uu * 20]);
        float4 A0 = base[0];   // comps 0..3
        float4 A1 = base[1];   // comps 4..7
        float4 A2 = base[2];   // comps 8..11
        float4 A3 = base[3];   // comps 12..15
        float wp = sWpre0[uu * 32 + lane];
        float w1 = sWeff[(0 * 16 + uu) * 32 + lane];
        float w2 = sWeff[(1 * 16 + uu) * 32 + lane];
        float w3 = sWeff[(2 * 16 + uu) * 32 + lane];
        r[0]  = fmaf(A0.x, wp, r[0]);
        r[1]  = fmaf(A0.y, w1, r[1]);
        r[2]  = fmaf(A0.z, w1, r[2]);
        r[3]  = fmaf(A0.w, w1, r[3]);
        r[4]  = fmaf(A1.x, w2, r[4]);
        r[5]  = fmaf(A1.y, w2, r[5]);
        r[6]  = fmaf(A1.z, w2, r[6]);
        r[7]  = fmaf(A1.w, w2, r[7]);
        r[8]  = fmaf(A2.x, w2, r[8]);
        r[9]  = fmaf(A2.y, w3, r[9]);
        r[10] = fmaf(A2.z, w3, r[10]);
        r[11] = fmaf(A2.w, w3, r[11]);
        r[12] = fmaf(A3.x, w3, r[12]);
        r[13] = fmaf(A3.y, w3, r[13]);
        r[14] = fmaf(A3.z, w3, r[14]);
        r[15] = fmaf(A3.w, w3, r[15]);
    }

    const float SCALE_L = 1.0f / (128.0f * 5.656854249492381f); // 1/(DENOM*sqrt(mul)*sqrt(tmul))
    // stage l>=1 outputs
#pragma unroll
    for (int j = 0; j < 3; j++) sQ[warp][32  + lane * 3 + j] = r[1 + j] * SCALE_L;
#pragma unroll
    for (int j = 0; j < 5; j++) sQ[warp][128 + lane * 5 + j] = r[4 + j] * SCALE_L;
#pragma unroll
    for (int j = 0; j < 7; j++) sQ[warp][288 + lane * 7 + j] = r[9 + j] * SCALE_L;

    // l = 0 path: pre -> gelu -> post, + shortcut
    float p = r[0] * (1.f / 128.f);           // /DENOM * inv_in
    // exact gelu * C_GELU, C = (E[gelu(z)^2])^{-1/2} = 1.5335285
    p = 1.5335285f * 0.5f * p * (1.f + erff(p * 0.7071067811865476f));
    sP0[warp][lane] = p;
    __syncwarp();
    float q0 = 0.f;
#pragma unroll
    for (int v = 0; v < 32; v++) q0 += sP0[warp][v] * sWpost0[v * 32 + lane];
    q0 *= 0.17677669529663687f;               // 1/sqrt(32)
    // shortcut: 4 x LDG.128 broadcast of this node's x row
    float sc = 0.f;
    {
        const float4* xr = reinterpret_cast<const float4*>(xin + (size_t)node * MULC);
#pragma unroll
        for (int g = 0; g < 4; g++) {
            float4 xg = xr[g];
            sc = fmaf(xg.x, sWsc[(g * 4 + 0) * 32 + lane], sc);
            sc = fmaf(xg.y, sWsc[(g * 4 + 1) * 32 + lane], sc);
            sc = fmaf(xg.z, sWsc[(g * 4 + 2) * 32 + lane], sc);
            sc = fmaf(xg.w, sWsc[(g * 4 + 3) * 32 + lane], sc);
        }
    }
    q0 += sc * 0.25f;                         // inv_in
    sQ[warp][lane] = q0;
    __syncwarp();

    // vectorized writeback: 4 x STG.128 per lane
    {
        float4*       op4 = reinterpret_cast<float4*>(out + (size_t)node * 512);
        const float4* sq4 = reinterpret_cast<const float4*>(sQ[warp]);
#pragma unroll
        for (int t = 0; t < 4; t++) op4[lane + 32 * t] = sq4[lane + 32 * t];
    }
}

extern "C" void kernel_launch(void* const* d_in, const int* in_sizes, int n_in,
                              void* d_out, int out_size) {
    const float* x     = (const float*)d_in[0];
    const float* pos   = (const float*)d_in[1];
    const float* Wpre  = (const float*)d_in[2];
    const float* Wpost = (const float*)d_in[3];
    const float* Wsc   = (const float*)d_in[4];
    const int*   send  = (const int*)d_in[5];
    const int*   recv  = (const int*)d_in[6];
    float*       out   = (float*)d_out;

    int n  = in_sizes[0] / MULC;  // 32768 nodes
    int e  = in_sizes[5];         // 1048576 edges
    int e4 = e / 4;

    k_pre<<<(e4 + 255) / 256, 256>>>(pos, Wpre, Wpost, (const int4*)recv, n, e4);
    k_scan<<<128, 256>>>(n, e);
    k_scatter<<<(e4 + 255) / 256, 256>>>((const int4*)send, (const int4*)recv, e4);
    k_main<<<n / 8, 256>>>(x, Wpre, Wpost, Wsc, out, n);
}

// round 9
// speedup vs baseline: 2.3623x; 1.0474x over previous
#include <cuda_runtime.h>
#include <math.h>

#define NN   32768
#define EE   1048576
#define MULC 16
#define TMULC 32

// ---- scratch (static device globals; no allocation allowed) ----
// INVARIANT: d_count is all-zero at entry to each kernel_launch call.
// (Zero at module load; k_scan re-zeroes it after consuming the counts.)
__device__ int    d_count[NN];
__device__ int    d_offsets[NN + 1];
__device__ int    d_cursor[NN];
__device__ int    d_sorted[EE];       // sender id per edge, grouped by receiver
__device__ float4 d_pos4[NN];
__device__ __align__(16) float d_Weff[3 * 16 * 32];
__device__ int    d_blocksum[128];    // scan aggregates; -1 = not ready (armed by k_pre)

// -------- pre: histogram + pack positions + W_eff + arm scan sentinels --
__global__ void k_pre(const float* __restrict__ pos,
                      const float* __restrict__ Wpre,
                      const float* __restrict__ Wpost,
                      const int4* __restrict__ recv4,
                      int n, int e4) {
    int i = blockIdx.x * blockDim.x + threadIdx.x;
    if (i < e4) {
        int4 r = recv4[i];
        atomicAdd(&d_count[r.x], 1);
        atomicAdd(&d_count[r.y], 1);
        atomicAdd(&d_count[r.z], 1);
        atomicAdd(&d_count[r.w], 1);
    }
    if (i < n) {
        d_pos4[i] = make_float4(pos[3 * i], pos[3 * i + 1], pos[3 * i + 2], 0.f);
    }
    if (i < 128) d_blocksum[i] = -1;      // arm lookback sentinels
    if (i < 3 * 16 * 32) {
        int ll = i >> 9;          // 0..2  -> irreps l = ll+1
        int u  = (i >> 5) & 15;
        int w  = i & 31;
        const float* A = Wpre  + (ll + 1) * MULC * TMULC + u * TMULC;
        const float* B = Wpost + (ll + 1) * TMULC * TMULC + w;
        float s = 0.f;
#pragma unroll
        for (int v = 0; v < TMULC; v++) s += A[v] * B[v * TMULC];
        d_Weff[i] = s;
    }
}

// ------ single-kernel exclusive scan via decoupled lookback -------------
// 128 blocks x 256 threads, all resident simultaneously (128 < 148 SMs).
__global__ void __launch_bounds__(256) k_scan(int n, int e) {
    __shared__ int sh[256];
    __shared__ int spre[128];
    __shared__ int prefbase;
    int tid = threadIdx.x;
    int bid = blockIdx.x;
    int i   = bid * 256 + tid;
    int v   = d_count[i];
    d_count[i] = 0;                       // restore invariant for next call
    sh[tid] = v;
    __syncthreads();
#pragma unroll
    for (int off = 1; off < 256; off <<= 1) {
        int a = (tid >= off) ? sh[tid - off] : 0;
        __syncthreads();
        sh[tid] += a;
        __syncthreads();
    }
    int incl = sh[tid];                   // inclusive block-local prefix
    if (tid == 255) atomicExch(&d_blocksum[bid], incl);  // publish aggregate
    // lookback: thread t spins on predecessor t's aggregate
    if (tid < bid) {
        int vv;
        do { vv = atomicAdd(&d_blocksum[tid], 0); } while (vv < 0);
        spre[tid] = vv;
    }
    __syncthreads();
    if (tid == 0) {
        int s = 0;
        for (int t = 0; t < bid; t++) s += spre[t];
        prefbase = s;
    }
    __syncthreads();
    int o = prefbase + incl - v;          // global exclusive prefix
    d_offsets[i] = o;
    d_cursor[i]  = o;
    if (i == n - 1) d_offsets[n] = e;
}

// -------- scatter sender ids into receiver-grouped order (4/thread) -----
__global__ void k_scatter(const int4* __restrict__ send4, const int4* __restrict__ recv4, int e4) {
    int i = blockIdx.x * blockDim.x + threadIdx.x;
    if (i < e4) {
        int4 s = send4[i];
        int4 r = recv4[i];
        d_sorted[atomicAdd(&d_cursor[r.x], 1)] = s.x;
        d_sorted[atomicAdd(&d_cursor[r.y], 1)] = s.y;
        d_sorted[atomicAdd(&d_cursor[r.z], 1)] = s.z;
        d_sorted[atomicAdd(&d_cursor[r.w], 1)] = s.w;
    }
}

// ---------------- main: per-node aggregation + fused node update --------
// One warp per node. Lane = (q = lane>>3 -> edge 4k+q, t = lane&7 -> u pair
// {2t, 2t+1}). 4 edges per round, no divergence. Each lane accumulates all
// 16 raw monomials for both of its u channels (acc[32]).
__global__ void __launch_bounds__(256)
k_main(const float* __restrict__ xin,
       const float* __restrict__ Wpre,
       const float* __restrict__ Wpost,
       const float* __restrict__ Wsc,
       float* __restrict__ out, int n) {
    __shared__ __align__(16) float sWeff[3 * 16 * 32];
    __shared__ __align__(16) float sWpre0[16 * 32];
    __shared__ __align__(16) float sWpost0[32 * 32];
    __shared__ __align__(16) float sWsc[16 * 32];
    __shared__ __align__(16) float sA[8][16 * 20];  // [u][comp] stride 20 (80B)
    __shared__ __align__(16) float sQ[8][512];      // per-warp staged output row
    __shared__ float sP0[8][32];                    // per-warp gelu intermediate

    int tid  = threadIdx.x;
    int warp = tid >> 5;
    int lane = tid & 31;
    int node = blockIdx.x * 8 + warp;
    int t    = lane & 7;
    int q    = lane >> 3;

    // --- issue the long-latency per-node loads BEFORE weight staging ----
    int nodeC = (node < n) ? node : (n - 1);
    int    beg = d_offsets[nodeC];
    int    end = d_offsets[nodeC + 1];
    float4 rp  = d_pos4[nodeC];
    int myE0   = beg + lane;
    int sid    = (myE0 < end) ? d_sorted[myE0] : 0;   // first tile prefetch

    // vectorized weight staging (float4)
    {
        const float4* W4;
        float4* S4;
        W4 = reinterpret_cast<const float4*>(d_Weff);
        S4 = reinterpret_cast<float4*>(sWeff);
        for (int k = tid; k < 384; k += 256) S4[k] = W4[k];
        W4 = reinterpret_cast<const float4*>(Wpre);
        S4 = reinterpret_cast<float4*>(sWpre0);
        for (int k = tid; k < 128; k += 256) S4[k] = W4[k];
        W4 = reinterpret_cast<const float4*>(Wpost);
        S4 = reinterpret_cast<float4*>(sWpost0);
        for (int k = tid; k < 256; k += 256) S4[k] = W4[k];
        W4 = reinterpret_cast<const float4*>(Wsc);
        S4 = reinterpret_cast<float4*>(sWsc);
        for (int k = tid; k < 128; k += 256) S4[k] = W4[k];
    }
    __syncthreads();
    if (node >= n) return;

    // acc[j*16+c]: raw monomial aggregates for u = 2t+j (this lane's octet edges)
    // c: 0=1 1=X 2=Y 3=Z 4=XY 5=YZ 6=ZZ 7=XZ
    //    8=P 9=YP 10=XP 11=Y*ZZ 12=X*ZZ 13=Z*ZZ 14=ZP 15=XYZ   (P=X^2-Y^2)
    float acc[32];
#pragma unroll
    for (int c = 0; c < 32; c++) acc[c] = 0.f;

    for (int t0 = beg; t0 < end; t0 += 32) {
        // prefetch next tile's sender ids while we compute this tile
        int nt  = t0 + 32;
        int nxt = 0;
        if (nt < end) {
            int e2 = nt + lane;
            nxt = (e2 < end) ? d_sorted[e2] : 0;
        }
        int cnt = end - t0;
        if (cnt > 32) cnt = 32;
        int rounds = (cnt + 3) >> 2;
#pragma unroll 2
        for (int k = 0; k < rounds; k++) {
            int    ei = 4 * k + q;
            int    s  = __shfl_sync(0xffffffffu, sid, ei);
            float4 sp = d_pos4[s];
            float2 xv = make_float2(0.f, 0.f);
            if (ei < cnt)
                xv = *reinterpret_cast<const float2*>(xin + s * MULC + 2 * t);
            float rx = rp.x - sp.x, ry = rp.y - sp.y, rz = rp.z - sp.z;
            float n2 = rx * rx + ry * ry + rz * rz;
            float iv = (n2 > 0.f) ? rsqrtf(n2) : 0.f;
            float X = rx * iv, Y = ry * iv, Z = rz * iv;
            float XY = X * Y, YZ = Y * Z, ZZ = Z * Z, XZ = X * Z;
            float P   = fmaf(X, X, -(Y * Y));
            float YP  = Y * P,  XP = X * P,  ZP = Z * P;
            float YZZ = YZ * Z, XZZ = XZ * Z, ZZZ = Z * ZZ, XYZ = XY * Z;
            acc[0]  += xv.x;
            acc[1]  = fmaf(xv.x, X,   acc[1]);
            acc[2]  = fmaf(xv.x, Y,   acc[2]);
            acc[3]  = fmaf(xv.x, Z,   acc[3]);
            acc[4]  = fmaf(xv.x, XY,  acc[4]);
            acc[5]  = fmaf(xv.x, YZ,  acc[5]);
            acc[6]  = fmaf(xv.x, ZZ,  acc[6]);
            acc[7]  = fmaf(xv.x, XZ,  acc[7]);
            acc[8]  = fmaf(xv.x, P,   acc[8]);
            acc[9]  = fmaf(xv.x, YP,  acc[9]);
            acc[10] = fmaf(xv.x, XP,  acc[10]);
            acc[11] = fmaf(xv.x, YZZ, acc[11]);
            acc[12] = fmaf(xv.x, XZZ, acc[12]);
            acc[13] = fmaf(xv.x, ZZZ, acc[13]);
            acc[14] = fmaf(xv.x, ZP,  acc[14]);
            acc[15] = fmaf(xv.x, XYZ, acc[15]);
            acc[16] += xv.y;
            acc[17] = fmaf(xv.y, X,   acc[17]);
            acc[18] = fmaf(xv.y, Y,   acc[18]);
            acc[19] = fmaf(xv.y, Z,   acc[19]);
            acc[20] = fmaf(xv.y, XY,  acc[20]);
            acc[21] = fmaf(xv.y, YZ,  acc[21]);
            acc[22] = fmaf(xv.y, ZZ,  acc[22]);
            acc[23] = fmaf(xv.y, XZ,  acc[23]);
            acc[24] = fmaf(xv.y, P,   acc[24]);
            acc[25] = fmaf(xv.y, YP,  acc[25]);
            acc[26] = fmaf(xv.y, XP,  acc[26]);
            acc[27] = fmaf(xv.y, YZZ, acc[27]);
            acc[28] = fmaf(xv.y, XZZ, acc[28]);
            acc[29] = fmaf(xv.y, ZZZ, acc[29]);
            acc[30] = fmaf(xv.y, ZP,  acc[30]);
            acc[31] = fmaf(xv.y, XYZ, acc[31]);
        }
        sid = nxt;
    }

    // merge across the 4 octets (lanes t, t+8, t+16, t+24)
#pragma unroll
    for (int c = 0; c < 32; c++) {
        acc[c] += __shfl_xor_sync(0xffffffffu, acc[c], 8);
        acc[c] += __shfl_xor_sync(0xffffffffu, acc[c], 16);
    }

    // ---- reconstruct normalized SH aggregates; lanes 0..7 store both u rows ----
    if (lane < 8) {
#pragma unroll
        for (int j = 0; j < 2; j++) {
            const float* a = acc + j * 16;
            float ys[16];
            ys[0]  = a[0];
            ys[1]  = 1.7320508075688772f * a[1];
            ys[2]  = 1.7320508075688772f * a[2];
            ys[3]  = 1.7320508075688772f * a[3];
            ys[4]  = 3.872983346207417f * a[4];
            ys[5]  = 3.872983346207417f * a[5];
            ys[6]  = 1.118033988749895f * (3.f * a[6] - a[0]);           // 0.5*sqrt(5)
            ys[7]  = 3.872983346207417f * a[7];
            ys[8]  = 1.9364916731037085f * a[8];                         // 0.5*sqrt(15)
            ys[9]  = 2.091650066335189f * (a[2] - a[11] + 2.f * a[9]);   // y(3xx-yy)
            ys[10] = 10.246950765959598f * a[15];                        // sqrt(105)
            ys[11] = 1.6201851746019651f * (5.f * a[11] - a[2]);         // sqrt(21/8)
            ys[12] = 1.3228756555322954f * (5.f * a[13] - 3.f * a[3]);   // 0.5*sqrt(7)
            ys[13] = 1.6201851746019651f * (5.f * a[12] - a[1]);
            ys[14] = 5.123475382979799f * a[14];                         // 0.5*sqrt(105)
            ys[15] = 2.091650066335189f * (2.f * a[10] + a[12] - a[1]);  // x(xx-3yy)
            float4* dst = reinterpret_cast<float4*>(&sA[warp][(2 * t + j) * 20]);
            dst[0] = make_float4(ys[0],  ys[1],  ys[2],  ys[3]);
            dst[1] = make_float4(ys[4],  ys[5],  ys[6],  ys[7]);
            dst[2] = make_float4(ys[8],  ys[9],  ys[10], ys[11]);
            dst[3] = make_float4(ys[12], ys[13], ys[14], ys[15]);
        }
    }
    __syncwarp();

    // ----- node update: r[i] = sum_u sA[u][i] * W(i-block)[u][lane] -----
    float r[16];
#pragma unroll
    for (int i = 0; i < 16; i++) r[i] = 0.f;
#pragma unroll
    for (int uu = 0; uu < 16; uu++) {
        const float4* base = reinterpret_cast<const float4*>(&sA[warp][uu * 20]);
        float4 A0 = base[0];   // comps 0..3
        float4 A1 = base[1];   // comps 4..7
        float4 A2 = base[2];   // comps 8..11
        float4 A3 = base[3];   // comps 12..15
        float wp = sWpre0[uu * 32 + lane];
        float w1 = sWeff[(0 * 16 + uu) * 32 + lane];
        float w2 = sWeff[(1 * 16 + uu) * 32 + lane];
        float w3 = sWeff[(2 * 16 + uu) * 32 + lane];
        r[0]  = fmaf(A0.x, wp, r[0]);
        r[1]  = fmaf(A0.y, w1, r[1]);
        r[2]  = fmaf(A0.z, w1, r[2]);
        r[3]  = fmaf(A0.w, w1, r[3]);
        r[4]  = fmaf(A1.x, w2, r[4]);
        r[5]  = fmaf(A1.y, w2, r[5]);
        r[6]  = fmaf(A1.z, w2, r[6]);
        r[7]  = fmaf(A1.w, w2, r[7]);
        r[8]  = fmaf(A2.x, w2, r[8]);
        r[9]  = fmaf(A2.y, w3, r[9]);
        r[10] = fmaf(A2.z, w3, r[10]);
        r[11] = fmaf(A2.w, w3, r[11]);
        r[12] = fmaf(A3.x, w3, r[12]);
        r[13] = fmaf(A3.y, w3, r[13]);
        r[14] = fmaf(A3.z, w3, r[14]);
        r[15] = fmaf(A3.w, w3, r[15]);
    }

    const float SCALE_L = 1.0f / (128.0f * 5.656854249492381f); // 1/(DENOM*sqrt(mul)*sqrt(tmul))
    // stage l>=1 outputs
#pragma unroll
    for (int j = 0; j < 3; j++) sQ[warp][32  + lane * 3 + j] = r[1 + j] * SCALE_L;
#pragma unroll
    for (int j = 0; j < 5; j++) sQ[warp][128 + lane * 5 + j] = r[4 + j] * SCALE_L;
#pragma unroll
    for (int j = 0; j < 7; j++) sQ[warp][288 + lane * 7 + j] = r[9 + j] * SCALE_L;

    // l = 0 path: pre -> gelu -> post, + shortcut
    float p = r[0] * (1.f / 128.f);           // /DENOM * inv_in
    // exact gelu * C_GELU, C = (E[gelu(z)^2])^{-1/2} = 1.5335285
    p = 1.5335285f * 0.5f * p * (1.f + erff(p * 0.7071067811865476f));
    sP0[warp][lane] = p;
    __syncwarp();
    float q0 = 0.f;
#pragma unroll
    for (int v = 0; v < 32; v++) q0 += sP0[warp][v] * sWpost0[v * 32 + lane];
    q0 *= 0.17677669529663687f;               // 1/sqrt(32)
    // shortcut: 4 x LDG.128 broadcast of this node's x row
    float sc = 0.f;
    {
        const float4* xr = reinterpret_cast<const float4*>(xin + (size_t)node * MULC);
#pragma unroll
        for (int g = 0; g < 4; g++) {
            float4 xg = xr[g];
            sc = fmaf(xg.x, sWsc[(g * 4 + 0) * 32 + lane], sc);
            sc = fmaf(xg.y, sWsc[(g * 4 + 1) * 32 + lane], sc);
            sc = fmaf(xg.z, sWsc[(g * 4 + 2) * 32 + lane], sc);
            sc = fmaf(xg.w, sWsc[(g * 4 + 3) * 32 + lane], sc);
        }
    }
    q0 += sc * 0.25f;                         // inv_in
    sQ[warp][lane] = q0;
    __syncwarp();

    // vectorized writeback: 4 x STG.128 per lane
    {
        float4*       op4 = reinterpret_cast<float4*>(out + (size_t)node * 512);
        const float4* sq4 = reinterpret_cast<const float4*>(sQ[warp]);
#pragma unroll
        for (int k = 0; k < 4; k++) op4[lane + 32 * k] = sq4[lane + 32 * k];
    }
}

extern "C" void kernel_launch(void* const* d_in, const int* in_sizes, int n_in,
                              void* d_out, int out_size) {
    const float* x     = (const float*)d_in[0];
    const float* pos   = (const float*)d_in[1];
    const float* Wpre  = (const float*)d_in[2];
    const float* Wpost = (const float*)d_in[3];
    const float* Wsc   = (const float*)d_in[4];
    const int*   send  = (const int*)d_in[5];
    const int*   recv  = (const int*)d_in[6];
    float*       out   = (float*)d_out;

    int n  = in_sizes[0] / MULC;  // 32768 nodes
    int e  = in_sizes[5];         // 1048576 edges
    int e4 = e / 4;

    k_pre<<<(e4 + 255) / 256, 256>>>(pos, Wpre, Wpost, (const int4*)recv, n, e4);
    k_scan<<<128, 256>>>(n, e);
    k_scatter<<<(e4 + 255) / 256, 256>>>((const int4*)send, (const int4*)recv, e4);
    k_main<<<n / 8, 256>>>(x, Wpre, Wpost, Wsc, out, n);
}